// round 7
// baseline (speedup 1.0000x reference)
#include <cuda_runtime.h>
#include <cuda_bf16.h>
#include <math.h>
#include <stdint.h>

// ---------------------------------------------------------------------------
// DiT block. All GEMM/attention operands pre-split into bf16 hi/lo planes;
// mainloops are pure cp.async + ldmatrix + mma.sync (3-term split, fp32 acc).
// GEMM tile 128x256x32 (warp 64x64), 3-stage pipeline.
// B=8, N=1024, M=128, C=1024, H=16, D=64, MLP=4096
// ---------------------------------------------------------------------------

#define Bc  8
#define Nn  1024
#define Mm  128
#define Cc  1024
#define Hh  16
#define Dd  64
#define MLPD 4096
#define ROWS (Bc * Nn)          // 8192

// ------------------------- scratch (device globals) ------------------------
__device__ float g_ada[Bc * 6 * Cc];
__device__ float g_x1[ROWS * Cc];
__device__ float g_x2[ROWS * Cc];

// activation planes (bf16 hi/lo)
__device__ __align__(16) __nv_bfloat16 g_hh[ROWS * Cc],   g_hl[ROWS * Cc];
__device__ __align__(16) __nv_bfloat16 g_qkvh[ROWS*3*Cc], g_qkvl[ROWS*3*Cc];
__device__ __align__(16) __nv_bfloat16 g_kvh[Bc*Mm*2*Cc], g_kvl[Bc*Mm*2*Cc];
__device__ __align__(16) __nv_bfloat16 g_cth[Bc*Mm*Cc],   g_ctl[Bc*Mm*Cc];
__device__ __align__(16) __nv_bfloat16 g_ath[ROWS * Cc],  g_atl[ROWS * Cc];
__device__ __align__(16) __nv_bfloat16 g_mlph[ROWS*MLPD], g_mlpl[ROWS*MLPD];

// transposed + bf16-split weights: [N][K] hi/lo planes
__device__ __align__(16) __nv_bfloat16 g_wqkv_h[Cc * 3 * Cc], g_wqkv_l[Cc * 3 * Cc];
__device__ __align__(16) __nv_bfloat16 g_wpsa_h[Cc * Cc],     g_wpsa_l[Cc * Cc];
__device__ __align__(16) __nv_bfloat16 g_wq_h[Cc * Cc],       g_wq_l[Cc * Cc];
__device__ __align__(16) __nv_bfloat16 g_wkv_h[Cc * 2 * Cc],  g_wkv_l[Cc * 2 * Cc];
__device__ __align__(16) __nv_bfloat16 g_wpca_h[Cc * Cc],     g_wpca_l[Cc * Cc];
__device__ __align__(16) __nv_bfloat16 g_wfc1_h[Cc * MLPD],   g_wfc1_l[Cc * MLPD];
__device__ __align__(16) __nv_bfloat16 g_wfc2_h[MLPD * Cc],   g_wfc2_l[MLPD * Cc];

// ------------------------------ ptx helpers --------------------------------
__device__ __forceinline__ uint32_t smem_u32(const void* p) {
    uint32_t a;
    asm("{ .reg .u64 t; cvta.to.shared.u64 t, %1; cvt.u32.u64 %0, t; }" : "=r"(a) : "l"(p));
    return a;
}
__device__ __forceinline__ void ldsm_x4(uint32_t& r0, uint32_t& r1, uint32_t& r2,
                                        uint32_t& r3, uint32_t a) {
    asm volatile("ldmatrix.sync.aligned.m8n8.x4.shared.b16 {%0,%1,%2,%3}, [%4];"
                 : "=r"(r0), "=r"(r1), "=r"(r2), "=r"(r3) : "r"(a));
}
__device__ __forceinline__ void ldsm_x4t(uint32_t& r0, uint32_t& r1, uint32_t& r2,
                                         uint32_t& r3, uint32_t a) {
    asm volatile("ldmatrix.sync.aligned.m8n8.x4.trans.shared.b16 {%0,%1,%2,%3}, [%4];"
                 : "=r"(r0), "=r"(r1), "=r"(r2), "=r"(r3) : "r"(a));
}
__device__ __forceinline__ void mma16816(float* d, const uint32_t* a, const uint32_t* b) {
    asm volatile(
        "mma.sync.aligned.m16n8k16.row.col.f32.bf16.bf16.f32 "
        "{%0,%1,%2,%3}, {%4,%5,%6,%7}, {%8,%9}, {%0,%1,%2,%3};"
        : "+f"(d[0]), "+f"(d[1]), "+f"(d[2]), "+f"(d[3])
        : "r"(a[0]), "r"(a[1]), "r"(a[2]), "r"(a[3]), "r"(b[0]), "r"(b[1]));
}
__device__ __forceinline__ void cp16(uint32_t dst, const void* src) {
    asm volatile("cp.async.cg.shared.global [%0], [%1], 16;" :: "r"(dst), "l"(src));
}
#define CP_COMMIT asm volatile("cp.async.commit_group;" ::: "memory")
#define CP_WAIT0  asm volatile("cp.async.wait_group 0;" ::: "memory")
#define CP_WAIT1  asm volatile("cp.async.wait_group 1;" ::: "memory")

// GEMM tile swizzle: 64B rows (4 chunks of 16B); valid for r in [0,256)
__device__ __forceinline__ uint32_t toff(int r, int c) {
    return ((uint32_t)r << 6) + ((uint32_t)((c ^ (r >> 1)) & 3) << 4);
}
// attention tile swizzle: 128B rows (8 chunks of 16B)
__device__ __forceinline__ uint32_t aoff(int r, int c) {
    return ((uint32_t)r << 7) + ((uint32_t)((c ^ (r & 7)) & 7) << 4);
}

// ------------------------------ misc helpers -------------------------------
__device__ __forceinline__ float gelu_tanh(float x) {
    float x3 = x * x * x;
    return 0.5f * x * (1.0f + tanhf(0.7978845608028654f * (x + 0.044715f * x3)));
}
__device__ __forceinline__ float block_sum_1024(float v) {
    __shared__ float red[8];
    __shared__ float bcast;
    int lane = threadIdx.x & 31, wid = threadIdx.x >> 5;
    #pragma unroll
    for (int o = 16; o; o >>= 1) v += __shfl_xor_sync(0xffffffffu, v, o);
    __syncthreads();
    if (lane == 0) red[wid] = v;
    __syncthreads();
    if (threadIdx.x == 0) {
        float t = 0.f;
        #pragma unroll
        for (int i = 0; i < 8; i++) t += red[i];
        bcast = t;
    }
    __syncthreads();
    return bcast;
}
__device__ __forceinline__ uint32_t packbf(float x, float y) {
    __nv_bfloat16 a = __float2bfloat16(x), b = __float2bfloat16(y);
    return ((uint32_t)__bfloat16_as_ushort(b) << 16) | __bfloat16_as_ushort(a);
}
__device__ __forceinline__ float lobf(float x) {
    return x - __bfloat162float(__float2bfloat16(x));
}

// -------------------- weight prep: W[K][N] -> Wt_hi/lo [N][K] ---------------
__global__ __launch_bounds__(256) void wprep_kernel(
    const float* __restrict__ W, __nv_bfloat16* __restrict__ Th,
    __nv_bfloat16* __restrict__ Tl, int K, int N)
{
    __shared__ float t[32][33];
    int n0 = blockIdx.x * 32, k0 = blockIdx.y * 32;
    int tx = threadIdx.x & 31, ty = threadIdx.x >> 5;
    #pragma unroll
    for (int i = 0; i < 32; i += 8)
        t[ty + i][tx] = W[(size_t)(k0 + ty + i) * N + n0 + tx];
    __syncthreads();
    #pragma unroll
    for (int i = 0; i < 32; i += 8) {
        float v = t[tx][ty + i];
        __nv_bfloat16 h = __float2bfloat16(v);
        __nv_bfloat16 l = __float2bfloat16(v - __bfloat162float(h));
        size_t o = (size_t)(n0 + ty + i) * K + k0 + tx;
        Th[o] = h; Tl[o] = l;
    }
}

// ------------------ c_text -> bf16 hi/lo planes ----------------------------
__global__ __launch_bounds__(256) void ct_split_kernel(
    const float* __restrict__ X, __nv_bfloat16* __restrict__ Ph,
    __nv_bfloat16* __restrict__ Pl)
{
    size_t i = ((size_t)blockIdx.x * 256 + threadIdx.x) * 4;
    float4 v = *(const float4*)(X + i);
    uint2 vh, vl;
    vh.x = packbf(v.x, v.y); vh.y = packbf(v.z, v.w);
    vl.x = packbf(lobf(v.x), lobf(v.y)); vl.y = packbf(lobf(v.z), lobf(v.w));
    *(uint2*)(Ph + i) = vh;
    *(uint2*)(Pl + i) = vl;
}

// ----------------------- ada = silu(c_dino) @ W_ada + b --------------------
__global__ __launch_bounds__(256) void ada_kernel(
    const float* __restrict__ cdino, const float* __restrict__ W,
    const float* __restrict__ bvec, float* __restrict__ out)
{
    __shared__ float s[Cc];
    int b = blockIdx.y, tid = threadIdx.x;
    for (int i = tid; i < Cc; i += 256) {
        float v = cdino[b * Cc + i];
        s[i] = v / (1.0f + __expf(-v));
    }
    __syncthreads();
    int n = blockIdx.x * 256 + tid;
    float acc = 0.f;
    #pragma unroll 4
    for (int k = 0; k < Cc; k++)
        acc = fmaf(s[k], W[(size_t)k * (6 * Cc) + n], acc);
    out[b * 6 * Cc + n] = acc + bvec[n];
}

// ---------- h = modulate(ln(x), shift, scale) -> bf16 hi/lo planes ---------
__global__ __launch_bounds__(256) void lnmod_kernel(
    const float* __restrict__ X, const float* __restrict__ ada,
    int shiftOff, __nv_bfloat16* __restrict__ Yh, __nv_bfloat16* __restrict__ Yl)
{
    int row = blockIdx.x;
    int b = row >> 10;
    const float* xr = X + (size_t)row * Cc;
    int c = threadIdx.x * 4;

    float4 v = *(const float4*)(xr + c);
    float mu = block_sum_1024(v.x + v.y + v.z + v.w) * (1.0f / Cc);
    float c0 = v.x - mu, c1 = v.y - mu, c2 = v.z - mu, c3 = v.w - mu;
    float var = block_sum_1024(c0*c0 + c1*c1 + c2*c2 + c3*c3) * (1.0f / Cc);
    float rstd = rsqrtf(var + 1e-6f);

    const float* sh = ada + b * 6 * Cc + shiftOff;
    const float* sc = sh + Cc;
    float4 shv = *(const float4*)(sh + c);
    float4 scv = *(const float4*)(sc + c);
    float4 o;
    o.x = c0 * rstd * (1.0f + scv.x) + shv.x;
    o.y = c1 * rstd * (1.0f + scv.y) + shv.y;
    o.z = c2 * rstd * (1.0f + scv.z) + shv.z;
    o.w = c3 * rstd * (1.0f + scv.w) + shv.w;
    uint2 vh, vl;
    vh.x = packbf(o.x, o.y); vh.y = packbf(o.z, o.w);
    vl.x = packbf(lobf(o.x), lobf(o.y)); vl.y = packbf(lobf(o.z), lobf(o.w));
    *(uint2*)(Yh + (size_t)row * Cc + c) = vh;
    *(uint2*)(Yl + (size_t)row * Cc + c) = vl;
}

// --------------------------- mma.sync GEMM ---------------------------------
// A, B pre-split bf16 planes [M][K]/[N][K]. Tile 128x256x32, 8 warps (2x4),
// warp tile 64x64, 3-stage cp.async pipeline.
// mode 0: Cf = D + bias (+res)        (fp32 out)
// mode 1: gelu(D + bias) -> Ch/Cl planes
// mode 2: D + bias -> Ch/Cl planes
#define PL_AH 0
#define PL_AL 8192
#define PL_BH 16384
#define PL_BL 32768
#define MSTAGE 49152
#define MM_SMEM (3 * MSTAGE)    // 147456
#define MBK 32

__global__ __launch_bounds__(256) void mm_gemm(
    const __nv_bfloat16* __restrict__ Ahp, const __nv_bfloat16* __restrict__ Alp,
    const __nv_bfloat16* __restrict__ Bhp, const __nv_bfloat16* __restrict__ Blp,
    const float* __restrict__ bias, const float* __restrict__ res,
    float* __restrict__ Cf, __nv_bfloat16* __restrict__ Ch,
    __nv_bfloat16* __restrict__ Cl, int N, int K, int mode)
{
    extern __shared__ char smem[];
    uint32_t sb = smem_u32(smem);
    const int tid = threadIdx.x, lane = tid & 31, warp = tid >> 5;
    const int wm = warp >> 2, wn = warp & 3;        // 2 x 4 warp grid
    const int row0 = blockIdx.y * 128, col0 = blockIdx.x * 256;

    const int lr_ = tid >> 1;
    const int cb_ = (tid & 1) * 2;
    const __nv_bfloat16* Agh = Ahp + (size_t)(row0 + lr_) * K + cb_ * 8;
    const __nv_bfloat16* Agl = Alp + (size_t)(row0 + lr_) * K + cb_ * 8;
    const __nv_bfloat16* Bgh  = Bhp + (size_t)(col0 + lr_) * K + cb_ * 8;
    const __nv_bfloat16* Bgl  = Blp + (size_t)(col0 + lr_) * K + cb_ * 8;
    const __nv_bfloat16* Bgh2 = Bgh + (size_t)128 * K;
    const __nv_bfloat16* Bgl2 = Bgl + (size_t)128 * K;
    const uint32_t sA0 = toff(lr_, cb_), sA1 = toff(lr_, cb_ + 1);

    float d[4][8][4];
    #pragma unroll
    for (int i = 0; i < 4; i++)
        #pragma unroll
        for (int j = 0; j < 8; j++)
            d[i][j][0] = d[i][j][1] = d[i][j][2] = d[i][j][3] = 0.f;

    const int nk = K / MBK;

    #define MM_ISSUE(kt, stg) do {                                         \
        uint32_t bse = sb + (stg) * MSTAGE;                                \
        const __nv_bfloat16* p_;                                           \
        p_ = Agh + (kt) * MBK;                                             \
        cp16(bse + PL_AH + sA0, p_); cp16(bse + PL_AH + sA1, p_ + 8);      \
        p_ = Agl + (kt) * MBK;                                             \
        cp16(bse + PL_AL + sA0, p_); cp16(bse + PL_AL + sA1, p_ + 8);      \
        p_ = Bgh + (kt) * MBK;                                             \
        cp16(bse + PL_BH + sA0, p_); cp16(bse + PL_BH + sA1, p_ + 8);      \
        p_ = Bgh2 + (kt) * MBK;                                            \
        cp16(bse + PL_BH + 8192 + sA0, p_); cp16(bse + PL_BH + 8192 + sA1, p_ + 8); \
        p_ = Bgl + (kt) * MBK;                                             \
        cp16(bse + PL_BL + sA0, p_); cp16(bse + PL_BL + sA1, p_ + 8);      \
        p_ = Bgl2 + (kt) * MBK;                                            \
        cp16(bse + PL_BL + 8192 + sA0, p_); cp16(bse + PL_BL + 8192 + sA1, p_ + 8); \
        CP_COMMIT;                                                         \
    } while (0)

    MM_ISSUE(0, 0);
    if (nk > 1) MM_ISSUE(1, 1);

    const int g = lane >> 3, lq = lane & 7;

    for (int kt = 0; kt < nk; kt++) {
        if (kt + 1 < nk) { CP_WAIT1; } else { CP_WAIT0; }
        __syncthreads();
        if (kt + 2 < nk) {
            int stg2 = (kt + 2) % 3;
            MM_ISSUE(kt + 2, stg2);
        }
        const uint32_t base = sb + (kt % 3) * MSTAGE;

        #pragma unroll
        for (int ks = 0; ks < 2; ks++) {
            uint32_t ah[4][4], al[4][4];
            const int arow = ((g & 1) << 3) + lq;
            const int acol = 2 * ks + (g >> 1);
            #pragma unroll
            for (int mi = 0; mi < 4; mi++) {
                uint32_t o = toff(wm * 64 + mi * 16 + arow, acol);
                ldsm_x4(ah[mi][0], ah[mi][1], ah[mi][2], ah[mi][3], base + PL_AH + o);
                ldsm_x4(al[mi][0], al[mi][1], al[mi][2], al[mi][3], base + PL_AL + o);
            }
            const int brow = ((g >> 1) << 3) + lq;
            const int bcol = 2 * ks + (g & 1);
            #pragma unroll
            for (int nh = 0; nh < 4; nh++) {
                uint32_t o = toff(wn * 64 + nh * 16 + brow, bcol);
                uint32_t h0, h1, h2, h3, e0, e1, e2, e3;
                ldsm_x4(h0, h1, h2, h3, base + PL_BH + o);
                ldsm_x4(e0, e1, e2, e3, base + PL_BL + o);
                uint32_t bhA[2] = {h0, h1}, bhB[2] = {h2, h3};
                uint32_t blA[2] = {e0, e1}, blB[2] = {e2, e3};
                #pragma unroll
                for (int mi = 0; mi < 4; mi++) {
                    mma16816(d[mi][nh*2],   ah[mi], bhA);
                    mma16816(d[mi][nh*2],   al[mi], bhA);
                    mma16816(d[mi][nh*2],   ah[mi], blA);
                    mma16816(d[mi][nh*2+1], ah[mi], bhB);
                    mma16816(d[mi][nh*2+1], al[mi], bhB);
                    mma16816(d[mi][nh*2+1], ah[mi], blB);
                }
            }
        }
    }

    // ---- epilogue ----
    const int rr = lane >> 2, cc2 = (lane & 3) * 2;
    #pragma unroll
    for (int mi = 0; mi < 4; mi++) {
        #pragma unroll
        for (int ni = 0; ni < 8; ni++) {
            int r0g = row0 + wm * 64 + mi * 16 + rr;
            int cg  = col0 + wn * 64 + ni * 8 + cc2;
            float b0 = bias[cg], b1 = bias[cg + 1];
            #pragma unroll
            for (int hrow = 0; hrow < 2; hrow++) {
                int r = r0g + hrow * 8;
                float v0 = d[mi][ni][hrow * 2 + 0] + b0;
                float v1 = d[mi][ni][hrow * 2 + 1] + b1;
                if (mode == 0) {
                    if (res) {
                        float2 rv = *(const float2*)(res + (size_t)r * N + cg);
                        v0 += rv.x; v1 += rv.y;
                    }
                    float2 o; o.x = v0; o.y = v1;
                    *(float2*)(Cf + (size_t)r * N + cg) = o;
                } else {
                    if (mode == 1) { v0 = gelu_tanh(v0); v1 = gelu_tanh(v1); }
                    *(uint32_t*)(Ch + (size_t)r * N + cg) = packbf(v0, v1);
                    *(uint32_t*)(Cl + (size_t)r * N + cg) = packbf(lobf(v0), lobf(v1));
                }
            }
        }
    }
}

// ------------------- tensor-core flash attention ---------------------------
// 4 warps, 64 q x 64 k tiles, D=64. All inputs pre-split bf16 planes.
#define AT_QH 0
#define AT_QL 8192
#define AT_KH 16384
#define AT_KL 24576
#define AT_VH 32768
#define AT_VL 40960
#define AT_MD 49152
#define AT_SMEM 49408

__global__ __launch_bounds__(128) void attn_tc(
    const __nv_bfloat16* __restrict__ Qh, const __nv_bfloat16* __restrict__ Ql,
    const __nv_bfloat16* __restrict__ Kh, const __nv_bfloat16* __restrict__ Kl,
    const __nv_bfloat16* __restrict__ Vh, const __nv_bfloat16* __restrict__ Vl,
    __nv_bfloat16* __restrict__ Oh, __nv_bfloat16* __restrict__ Ol,
    const int* __restrict__ maskp,
    int qStride, int kvStride, int Lk, float scale)
{
    extern __shared__ char smem[];
    uint32_t sb = smem_u32(smem);
    const int tid = threadIdx.x, lane = tid & 31, warp = tid >> 5;
    const int b = blockIdx.z, h = blockIdx.y, n0 = blockIdx.x * 64;
    const int w16 = warp * 16;

    #pragma unroll
    for (int it = 0; it < 4; it++) {
        int cid = tid + it * 128;
        int r = cid >> 3, c = cid & 7;
        size_t gq = (size_t)(b * Nn + n0 + r) * qStride + h * Dd + c * 8;
        uint32_t o = aoff(r, c);
        cp16(sb + AT_QH + o, Qh + gq);
        cp16(sb + AT_QL + o, Ql + gq);
    }
    CP_COMMIT; CP_WAIT0;
    __syncthreads();

    uint32_t qh[4][4], ql[4][4];
    {
        int rr = (lane & 7) + 8 * ((lane >> 3) & 1);
        int cc = lane >> 4;
        #pragma unroll
        for (int kc = 0; kc < 4; kc++) {
            uint32_t o = aoff(w16 + rr, kc * 2 + cc);
            ldsm_x4(qh[kc][0], qh[kc][1], qh[kc][2], qh[kc][3], sb + AT_QH + o);
            ldsm_x4(ql[kc][0], ql[kc][1], ql[kc][2], ql[kc][3], sb + AT_QL + o);
        }
    }

    float o_[8][4];
    #pragma unroll
    for (int i = 0; i < 8; i++) { o_[i][0]=o_[i][1]=o_[i][2]=o_[i][3]=0.f; }
    float m0 = -INFINITY, m1 = -INFINITY, l0 = 0.f, l1 = 0.f;

    const int krow = (lane & 7) + 8 * (lane >> 4);
    const int kcsel = (lane >> 3) & 1;
    const int vrow = lane & 15, vcsel = lane >> 4;
    const float* madd = (const float*)(smem + AT_MD);

    const int nTiles = Lk >> 6;
    for (int kt = 0; kt < nTiles; kt++) {
        __syncthreads();
        #pragma unroll
        for (int it = 0; it < 4; it++) {
            int cid = tid + it * 128;
            int r = cid >> 3, c = cid & 7;
            size_t gk = (size_t)(b * Lk + kt * 64 + r) * kvStride + h * Dd + c * 8;
            uint32_t o = aoff(r, c);
            cp16(sb + AT_KH + o, Kh + gk);
            cp16(sb + AT_KL + o, Kl + gk);
            cp16(sb + AT_VH + o, Vh + gk);
            cp16(sb + AT_VL + o, Vl + gk);
        }
        if (maskp && tid < 64)
            ((float*)(smem + AT_MD))[tid] =
                maskp[b * Lk + kt * 64 + tid] ? 0.f : -1e30f;
        CP_COMMIT; CP_WAIT0;
        __syncthreads();

        float s[8][4];
        #pragma unroll
        for (int i = 0; i < 8; i++) { s[i][0]=s[i][1]=s[i][2]=s[i][3]=0.f; }
        #pragma unroll
        for (int kc = 0; kc < 4; kc++) {
            #pragma unroll
            for (int np = 0; np < 4; np++) {
                uint32_t o = aoff(np * 16 + krow, kc * 2 + kcsel);
                uint32_t h0, h1, h2, h3, e0, e1, e2, e3;
                ldsm_x4(h0, h1, h2, h3, sb + AT_KH + o);
                ldsm_x4(e0, e1, e2, e3, sb + AT_KL + o);
                uint32_t bhA[2] = {h0, h1}, bhB[2] = {h2, h3};
                uint32_t blA[2] = {e0, e1}, blB[2] = {e2, e3};
                mma16816(s[np*2],   qh[kc], bhA);
                mma16816(s[np*2],   ql[kc], bhA);
                mma16816(s[np*2],   qh[kc], blA);
                mma16816(s[np*2+1], qh[kc], bhB);
                mma16816(s[np*2+1], ql[kc], bhB);
                mma16816(s[np*2+1], qh[kc], blB);
            }
        }
        #pragma unroll
        for (int nt = 0; nt < 8; nt++) {
            s[nt][0] *= scale; s[nt][1] *= scale;
            s[nt][2] *= scale; s[nt][3] *= scale;
        }
        if (maskp) {
            int cbase = 2 * (lane & 3);
            #pragma unroll
            for (int nt = 0; nt < 8; nt++) {
                float mA = madd[nt * 8 + cbase], mB = madd[nt * 8 + cbase + 1];
                s[nt][0] += mA; s[nt][1] += mB;
                s[nt][2] += mA; s[nt][3] += mB;
            }
        }
        float lm0 = -INFINITY, lm1 = -INFINITY;
        #pragma unroll
        for (int nt = 0; nt < 8; nt++) {
            lm0 = fmaxf(lm0, fmaxf(s[nt][0], s[nt][1]));
            lm1 = fmaxf(lm1, fmaxf(s[nt][2], s[nt][3]));
        }
        lm0 = fmaxf(lm0, __shfl_xor_sync(0xffffffffu, lm0, 1));
        lm0 = fmaxf(lm0, __shfl_xor_sync(0xffffffffu, lm0, 2));
        lm1 = fmaxf(lm1, __shfl_xor_sync(0xffffffffu, lm1, 1));
        lm1 = fmaxf(lm1, __shfl_xor_sync(0xffffffffu, lm1, 2));
        float mn0 = fmaxf(m0, lm0), mn1 = fmaxf(m1, lm1);
        float cr0 = __expf(m0 - mn0), cr1 = __expf(m1 - mn1);
        float sum0 = 0.f, sum1 = 0.f;
        #pragma unroll
        for (int nt = 0; nt < 8; nt++) {
            s[nt][0] = __expf(s[nt][0] - mn0); sum0 += s[nt][0];
            s[nt][1] = __expf(s[nt][1] - mn0); sum0 += s[nt][1];
            s[nt][2] = __expf(s[nt][2] - mn1); sum1 += s[nt][2];
            s[nt][3] = __expf(s[nt][3] - mn1); sum1 += s[nt][3];
        }
        sum0 += __shfl_xor_sync(0xffffffffu, sum0, 1);
        sum0 += __shfl_xor_sync(0xffffffffu, sum0, 2);
        sum1 += __shfl_xor_sync(0xffffffffu, sum1, 1);
        sum1 += __shfl_xor_sync(0xffffffffu, sum1, 2);
        l0 = l0 * cr0 + sum0; l1 = l1 * cr1 + sum1;
        m0 = mn0; m1 = mn1;
        #pragma unroll
        for (int nt = 0; nt < 8; nt++) {
            o_[nt][0] *= cr0; o_[nt][1] *= cr0;
            o_[nt][2] *= cr1; o_[nt][3] *= cr1;
        }
        #pragma unroll
        for (int kc = 0; kc < 4; kc++) {
            uint32_t pah[4], pal[4];
            float* sA = s[kc * 2];
            float* sB = s[kc * 2 + 1];
            pah[0] = packbf(sA[0], sA[1]); pah[1] = packbf(sA[2], sA[3]);
            pah[2] = packbf(sB[0], sB[1]); pah[3] = packbf(sB[2], sB[3]);
            pal[0] = packbf(lobf(sA[0]), lobf(sA[1]));
            pal[1] = packbf(lobf(sA[2]), lobf(sA[3]));
            pal[2] = packbf(lobf(sB[0]), lobf(sB[1]));
            pal[3] = packbf(lobf(sB[2]), lobf(sB[3]));
            #pragma unroll
            for (int dp = 0; dp < 4; dp++) {
                uint32_t o = aoff(kc * 16 + vrow, dp * 2 + vcsel);
                uint32_t v0, v1, v2, v3, u0, u1, u2, u3;
                ldsm_x4t(v0, v1, v2, v3, sb + AT_VH + o);
                ldsm_x4t(u0, u1, u2, u3, sb + AT_VL + o);
                uint32_t bhA[2] = {v0, v1}, bhB[2] = {v2, v3};
                uint32_t blA[2] = {u0, u1}, blB[2] = {u2, u3};
                mma16816(o_[dp*2],   pah, bhA);
                mma16816(o_[dp*2],   pal, bhA);
                mma16816(o_[dp*2],   pah, blA);
                mma16816(o_[dp*2+1], pah, bhB);
                mma16816(o_[dp*2+1], pal, bhB);
                mma16816(o_[dp*2+1], pah, blB);
            }
        }
    }

    float inv0 = 1.0f / l0, inv1 = 1.0f / l1;
    int r0 = w16 + (lane >> 2);
    int cg = h * Dd + 2 * (lane & 3);
    size_t rb = (size_t)(b * Nn + n0);
    #pragma unroll
    for (int nt = 0; nt < 8; nt++) {
        float v0 = o_[nt][0] * inv0, v1 = o_[nt][1] * inv0;
        float w0 = o_[nt][2] * inv1, w1 = o_[nt][3] * inv1;
        size_t o0 = (rb + r0) * Cc + cg + nt * 8;
        size_t o1 = (rb + r0 + 8) * Cc + cg + nt * 8;
        *(uint32_t*)(Oh + o0) = packbf(v0, v1);
        *(uint32_t*)(Ol + o0) = packbf(lobf(v0), lobf(v1));
        *(uint32_t*)(Oh + o1) = packbf(w0, w1);
        *(uint32_t*)(Ol + o1) = packbf(lobf(w0), lobf(w1));
    }
}

// ------------------------------- launch ------------------------------------
static void* sym_addr(const void* sym) {
    void* p = nullptr;
    cudaGetSymbolAddress(&p, sym);
    return p;
}

extern "C" void kernel_launch(void* const* d_in, const int* in_sizes, int n_in,
                              void* d_out, int out_size)
{
    const float* x        = (const float*)d_in[0];
    const float* c_dino   = (const float*)d_in[1];
    const float* c_text   = (const float*)d_in[2];
    const int*   mask     = (const int*)  d_in[3];
    const float* W_ada    = (const float*)d_in[4];
    const float* b_ada    = (const float*)d_in[5];
    const float* W_qkv    = (const float*)d_in[6];
    const float* b_qkv    = (const float*)d_in[7];
    const float* W_psa    = (const float*)d_in[8];
    const float* b_psa    = (const float*)d_in[9];
    const float* W_q      = (const float*)d_in[10];
    const float* b_q      = (const float*)d_in[11];
    const float* W_kv     = (const float*)d_in[12];
    const float* b_kv     = (const float*)d_in[13];
    const float* W_pca    = (const float*)d_in[14];
    const float* b_pca    = (const float*)d_in[15];
    const float* W_fc1    = (const float*)d_in[16];
    const float* b_fc1    = (const float*)d_in[17];
    const float* W_fc2    = (const float*)d_in[18];
    const float* b_fc2    = (const float*)d_in[19];
    float* out = (float*)d_out;

    float* ada  = (float*)sym_addr(g_ada);
    float* x1   = (float*)sym_addr(g_x1);
    float* x2   = (float*)sym_addr(g_x2);

    __nv_bfloat16* hh   = (__nv_bfloat16*)sym_addr(g_hh);
    __nv_bfloat16* hl   = (__nv_bfloat16*)sym_addr(g_hl);
    __nv_bfloat16* qkvh = (__nv_bfloat16*)sym_addr(g_qkvh);
    __nv_bfloat16* qkvl = (__nv_bfloat16*)sym_addr(g_qkvl);
    __nv_bfloat16* kvh  = (__nv_bfloat16*)sym_addr(g_kvh);
    __nv_bfloat16* kvl  = (__nv_bfloat16*)sym_addr(g_kvl);
    __nv_bfloat16* cth  = (__nv_bfloat16*)sym_addr(g_cth);
    __nv_bfloat16* ctl  = (__nv_bfloat16*)sym_addr(g_ctl);
    __nv_bfloat16* ath  = (__nv_bfloat16*)sym_addr(g_ath);
    __nv_bfloat16* atl  = (__nv_bfloat16*)sym_addr(g_atl);
    __nv_bfloat16* mlph = (__nv_bfloat16*)sym_addr(g_mlph);
    __nv_bfloat16* mlpl = (__nv_bfloat16*)sym_addr(g_mlpl);

    __nv_bfloat16* wqkv_h = (__nv_bfloat16*)sym_addr(g_wqkv_h);
    __nv_bfloat16* wqkv_l = (__nv_bfloat16*)sym_addr(g_wqkv_l);
    __nv_bfloat16* wpsa_h = (__nv_bfloat16*)sym_addr(g_wpsa_h);
    __nv_bfloat16* wpsa_l = (__nv_bfloat16*)sym_addr(g_wpsa_l);
    __nv_bfloat16* wq_h   = (__nv_bfloat16*)sym_addr(g_wq_h);
    __nv_bfloat16* wq_l   = (__nv_bfloat16*)sym_addr(g_wq_l);
    __nv_bfloat16* wkv_h  = (__nv_bfloat16*)sym_addr(g_wkv_h);
    __nv_bfloat16* wkv_l  = (__nv_bfloat16*)sym_addr(g_wkv_l);
    __nv_bfloat16* wpca_h = (__nv_bfloat16*)sym_addr(g_wpca_h);
    __nv_bfloat16* wpca_l = (__nv_bfloat16*)sym_addr(g_wpca_l);
    __nv_bfloat16* wfc1_h = (__nv_bfloat16*)sym_addr(g_wfc1_h);
    __nv_bfloat16* wfc1_l = (__nv_bfloat16*)sym_addr(g_wfc1_l);
    __nv_bfloat16* wfc2_h = (__nv_bfloat16*)sym_addr(g_wfc2_h);
    __nv_bfloat16* wfc2_l = (__nv_bfloat16*)sym_addr(g_wfc2_l);

    cudaFuncSetAttribute(attn_tc, cudaFuncAttributeMaxDynamicSharedMemorySize, AT_SMEM);
    cudaFuncSetAttribute(mm_gemm, cudaFuncAttributeMaxDynamicSharedMemorySize, MM_SMEM);

    // ---- weight prep ----
    wprep_kernel<<<dim3(3*Cc/32, Cc/32), 256>>>(W_qkv, wqkv_h, wqkv_l, Cc, 3*Cc);
    wprep_kernel<<<dim3(Cc/32,   Cc/32), 256>>>(W_psa, wpsa_h, wpsa_l, Cc, Cc);
    wprep_kernel<<<dim3(Cc/32,   Cc/32), 256>>>(W_q,   wq_h,   wq_l,   Cc, Cc);
    wprep_kernel<<<dim3(2*Cc/32, Cc/32), 256>>>(W_kv,  wkv_h,  wkv_l,  Cc, 2*Cc);
    wprep_kernel<<<dim3(Cc/32,   Cc/32), 256>>>(W_pca, wpca_h, wpca_l, Cc, Cc);
    wprep_kernel<<<dim3(MLPD/32, Cc/32), 256>>>(W_fc1, wfc1_h, wfc1_l, Cc, MLPD);
    wprep_kernel<<<dim3(Cc/32, MLPD/32), 256>>>(W_fc2, wfc2_h, wfc2_l, MLPD, Cc);

    ada_kernel<<<dim3(24, Bc), 256>>>(c_dino, W_ada, b_ada, ada);
    ct_split_kernel<<<(Bc*Mm*Cc)/1024, 256>>>(c_text, cth, ctl);

    // ---- self attention ----
    lnmod_kernel<<<ROWS, 256>>>(x, ada, 0, hh, hl);
    mm_gemm<<<dim3(3*Cc/256, ROWS/128), 256, MM_SMEM>>>(
        hh, hl, wqkv_h, wqkv_l, b_qkv, nullptr, nullptr, qkvh, qkvl, 3*Cc, Cc, 2);
    attn_tc<<<dim3(Nn/64, Hh, Bc), 128, AT_SMEM>>>(
        qkvh, qkvl, qkvh + Cc, qkvl + Cc, qkvh + 2*Cc, qkvl + 2*Cc,
        ath, atl, nullptr, 3*Cc, 3*Cc, Nn, 0.125f);
    mm_gemm<<<dim3(Cc/256, ROWS/128), 256, MM_SMEM>>>(
        ath, atl, wpsa_h, wpsa_l, b_psa, x, x1, nullptr, nullptr, Cc, Cc, 0);

    // ---- cross attention ----
    lnmod_kernel<<<ROWS, 256>>>(x1, ada, 2*Cc, hh, hl);
    mm_gemm<<<dim3(Cc/256, ROWS/128), 256, MM_SMEM>>>(
        hh, hl, wq_h, wq_l, b_q, nullptr, nullptr, qkvh, qkvl, Cc, Cc, 2);
    mm_gemm<<<dim3(2*Cc/256, (Bc*Mm)/128), 256, MM_SMEM>>>(
        cth, ctl, wkv_h, wkv_l, b_kv, nullptr, nullptr, kvh, kvl, 2*Cc, Cc, 2);
    attn_tc<<<dim3(Nn/64, Hh, Bc), 128, AT_SMEM>>>(
        qkvh, qkvl, kvh, kvl, kvh + Cc, kvl + Cc,
        ath, atl, mask, Cc, 2*Cc, Mm, 0.125f);
    mm_gemm<<<dim3(Cc/256, ROWS/128), 256, MM_SMEM>>>(
        ath, atl, wpca_h, wpca_l, b_pca, x1, x2, nullptr, nullptr, Cc, Cc, 0);

    // ---- MLP ----
    lnmod_kernel<<<ROWS, 256>>>(x2, ada, 4*Cc, hh, hl);
    mm_gemm<<<dim3(MLPD/256, ROWS/128), 256, MM_SMEM>>>(
        hh, hl, wfc1_h, wfc1_l, b_fc1, nullptr, nullptr, mlph, mlpl, MLPD, Cc, 1);
    mm_gemm<<<dim3(Cc/256, ROWS/128), 256, MM_SMEM>>>(
        mlph, mlpl, wfc2_h, wfc2_l, b_fc2, x2, out, nullptr, nullptr, Cc, MLPD, 0);
}

// round 8
// speedup vs baseline: 1.0636x; 1.0636x over previous
#include <cuda_runtime.h>
#include <cuda_bf16.h>
#include <math.h>
#include <stdint.h>

// ---------------------------------------------------------------------------
// DiT block. All GEMM/attention operands pre-split into bf16 hi/lo planes;
// mainloops are pure cp.async + ldmatrix + mma.sync (3-term split, fp32 acc).
// GEMM tile 128x128x32 (warp 64x32), 3-stage pipeline, term-outer MMA order.
// B=8, N=1024, M=128, C=1024, H=16, D=64, MLP=4096
// ---------------------------------------------------------------------------

#define Bc  8
#define Nn  1024
#define Mm  128
#define Cc  1024
#define Hh  16
#define Dd  64
#define MLPD 4096
#define ROWS (Bc * Nn)          // 8192

// ------------------------- scratch (device globals) ------------------------
__device__ float g_ada[Bc * 6 * Cc];
__device__ float g_x1[ROWS * Cc];
__device__ float g_x2[ROWS * Cc];

// activation planes (bf16 hi/lo)
__device__ __align__(16) __nv_bfloat16 g_hh[ROWS * Cc],   g_hl[ROWS * Cc];
__device__ __align__(16) __nv_bfloat16 g_qkvh[ROWS*3*Cc], g_qkvl[ROWS*3*Cc];
__device__ __align__(16) __nv_bfloat16 g_kvh[Bc*Mm*2*Cc], g_kvl[Bc*Mm*2*Cc];
__device__ __align__(16) __nv_bfloat16 g_cth[Bc*Mm*Cc],   g_ctl[Bc*Mm*Cc];
__device__ __align__(16) __nv_bfloat16 g_ath[ROWS * Cc],  g_atl[ROWS * Cc];
__device__ __align__(16) __nv_bfloat16 g_mlph[ROWS*MLPD], g_mlpl[ROWS*MLPD];

// transposed + bf16-split weights: [N][K] hi/lo planes
__device__ __align__(16) __nv_bfloat16 g_wqkv_h[Cc * 3 * Cc], g_wqkv_l[Cc * 3 * Cc];
__device__ __align__(16) __nv_bfloat16 g_wpsa_h[Cc * Cc],     g_wpsa_l[Cc * Cc];
__device__ __align__(16) __nv_bfloat16 g_wq_h[Cc * Cc],       g_wq_l[Cc * Cc];
__device__ __align__(16) __nv_bfloat16 g_wkv_h[Cc * 2 * Cc],  g_wkv_l[Cc * 2 * Cc];
__device__ __align__(16) __nv_bfloat16 g_wpca_h[Cc * Cc],     g_wpca_l[Cc * Cc];
__device__ __align__(16) __nv_bfloat16 g_wfc1_h[Cc * MLPD],   g_wfc1_l[Cc * MLPD];
__device__ __align__(16) __nv_bfloat16 g_wfc2_h[MLPD * Cc],   g_wfc2_l[MLPD * Cc];

// ------------------------------ ptx helpers --------------------------------
__device__ __forceinline__ uint32_t smem_u32(const void* p) {
    uint32_t a;
    asm("{ .reg .u64 t; cvta.to.shared.u64 t, %1; cvt.u32.u64 %0, t; }" : "=r"(a) : "l"(p));
    return a;
}
__device__ __forceinline__ void ldsm_x4(uint32_t& r0, uint32_t& r1, uint32_t& r2,
                                        uint32_t& r3, uint32_t a) {
    asm volatile("ldmatrix.sync.aligned.m8n8.x4.shared.b16 {%0,%1,%2,%3}, [%4];"
                 : "=r"(r0), "=r"(r1), "=r"(r2), "=r"(r3) : "r"(a));
}
__device__ __forceinline__ void ldsm_x4t(uint32_t& r0, uint32_t& r1, uint32_t& r2,
                                         uint32_t& r3, uint32_t a) {
    asm volatile("ldmatrix.sync.aligned.m8n8.x4.trans.shared.b16 {%0,%1,%2,%3}, [%4];"
                 : "=r"(r0), "=r"(r1), "=r"(r2), "=r"(r3) : "r"(a));
}
__device__ __forceinline__ void mma16816(float* d, const uint32_t* a, const uint32_t* b) {
    asm volatile(
        "mma.sync.aligned.m16n8k16.row.col.f32.bf16.bf16.f32 "
        "{%0,%1,%2,%3}, {%4,%5,%6,%7}, {%8,%9}, {%0,%1,%2,%3};"
        : "+f"(d[0]), "+f"(d[1]), "+f"(d[2]), "+f"(d[3])
        : "r"(a[0]), "r"(a[1]), "r"(a[2]), "r"(a[3]), "r"(b[0]), "r"(b[1]));
}
__device__ __forceinline__ void cp16(uint32_t dst, const void* src) {
    asm volatile("cp.async.cg.shared.global [%0], [%1], 16;" :: "r"(dst), "l"(src));
}
#define CP_COMMIT asm volatile("cp.async.commit_group;" ::: "memory")
#define CP_WAIT0  asm volatile("cp.async.wait_group 0;" ::: "memory")
#define CP_WAIT1  asm volatile("cp.async.wait_group 1;" ::: "memory")

// GEMM tile swizzle: 64B rows (4 chunks of 16B)
__device__ __forceinline__ uint32_t toff(int r, int c) {
    return ((uint32_t)r << 6) + ((uint32_t)((c ^ (r >> 1)) & 3) << 4);
}
// attention tile swizzle: 128B rows (8 chunks of 16B)
__device__ __forceinline__ uint32_t aoff(int r, int c) {
    return ((uint32_t)r << 7) + ((uint32_t)((c ^ (r & 7)) & 7) << 4);
}

// ------------------------------ misc helpers -------------------------------
__device__ __forceinline__ float gelu_tanh(float x) {
    float x3 = x * x * x;
    return 0.5f * x * (1.0f + tanhf(0.7978845608028654f * (x + 0.044715f * x3)));
}
__device__ __forceinline__ float block_sum_1024(float v) {
    __shared__ float red[8];
    __shared__ float bcast;
    int lane = threadIdx.x & 31, wid = threadIdx.x >> 5;
    #pragma unroll
    for (int o = 16; o; o >>= 1) v += __shfl_xor_sync(0xffffffffu, v, o);
    __syncthreads();
    if (lane == 0) red[wid] = v;
    __syncthreads();
    if (threadIdx.x == 0) {
        float t = 0.f;
        #pragma unroll
        for (int i = 0; i < 8; i++) t += red[i];
        bcast = t;
    }
    __syncthreads();
    return bcast;
}
__device__ __forceinline__ uint32_t packbf(float x, float y) {
    __nv_bfloat16 a = __float2bfloat16(x), b = __float2bfloat16(y);
    return ((uint32_t)__bfloat16_as_ushort(b) << 16) | __bfloat16_as_ushort(a);
}
__device__ __forceinline__ float lobf(float x) {
    return x - __bfloat162float(__float2bfloat16(x));
}

// -------------------- weight prep: W[K][N] -> Wt_hi/lo [N][K] ---------------
__global__ __launch_bounds__(256) void wprep_kernel(
    const float* __restrict__ W, __nv_bfloat16* __restrict__ Th,
    __nv_bfloat16* __restrict__ Tl, int K, int N)
{
    __shared__ float t[32][33];
    int n0 = blockIdx.x * 32, k0 = blockIdx.y * 32;
    int tx = threadIdx.x & 31, ty = threadIdx.x >> 5;
    #pragma unroll
    for (int i = 0; i < 32; i += 8)
        t[ty + i][tx] = W[(size_t)(k0 + ty + i) * N + n0 + tx];
    __syncthreads();
    #pragma unroll
    for (int i = 0; i < 32; i += 8) {
        float v = t[tx][ty + i];
        __nv_bfloat16 h = __float2bfloat16(v);
        __nv_bfloat16 l = __float2bfloat16(v - __bfloat162float(h));
        size_t o = (size_t)(n0 + ty + i) * K + k0 + tx;
        Th[o] = h; Tl[o] = l;
    }
}

// ------------------ c_text -> bf16 hi/lo planes ----------------------------
__global__ __launch_bounds__(256) void ct_split_kernel(
    const float* __restrict__ X, __nv_bfloat16* __restrict__ Ph,
    __nv_bfloat16* __restrict__ Pl)
{
    size_t i = ((size_t)blockIdx.x * 256 + threadIdx.x) * 4;
    float4 v = *(const float4*)(X + i);
    uint2 vh, vl;
    vh.x = packbf(v.x, v.y); vh.y = packbf(v.z, v.w);
    vl.x = packbf(lobf(v.x), lobf(v.y)); vl.y = packbf(lobf(v.z), lobf(v.w));
    *(uint2*)(Ph + i) = vh;
    *(uint2*)(Pl + i) = vl;
}

// ----------------------- ada = silu(c_dino) @ W_ada + b --------------------
__global__ __launch_bounds__(256) void ada_kernel(
    const float* __restrict__ cdino, const float* __restrict__ W,
    const float* __restrict__ bvec, float* __restrict__ out)
{
    __shared__ float s[Cc];
    int b = blockIdx.y, tid = threadIdx.x;
    for (int i = tid; i < Cc; i += 256) {
        float v = cdino[b * Cc + i];
        s[i] = v / (1.0f + __expf(-v));
    }
    __syncthreads();
    int n = blockIdx.x * 256 + tid;
    float acc = 0.f;
    #pragma unroll 4
    for (int k = 0; k < Cc; k++)
        acc = fmaf(s[k], W[(size_t)k * (6 * Cc) + n], acc);
    out[b * 6 * Cc + n] = acc + bvec[n];
}

// ---------- h = modulate(ln(x), shift, scale) -> bf16 hi/lo planes ---------
__global__ __launch_bounds__(256) void lnmod_kernel(
    const float* __restrict__ X, const float* __restrict__ ada,
    int shiftOff, __nv_bfloat16* __restrict__ Yh, __nv_bfloat16* __restrict__ Yl)
{
    int row = blockIdx.x;
    int b = row >> 10;
    const float* xr = X + (size_t)row * Cc;
    int c = threadIdx.x * 4;

    float4 v = *(const float4*)(xr + c);
    float mu = block_sum_1024(v.x + v.y + v.z + v.w) * (1.0f / Cc);
    float c0 = v.x - mu, c1 = v.y - mu, c2 = v.z - mu, c3 = v.w - mu;
    float var = block_sum_1024(c0*c0 + c1*c1 + c2*c2 + c3*c3) * (1.0f / Cc);
    float rstd = rsqrtf(var + 1e-6f);

    const float* sh = ada + b * 6 * Cc + shiftOff;
    const float* sc = sh + Cc;
    float4 shv = *(const float4*)(sh + c);
    float4 scv = *(const float4*)(sc + c);
    float4 o;
    o.x = c0 * rstd * (1.0f + scv.x) + shv.x;
    o.y = c1 * rstd * (1.0f + scv.y) + shv.y;
    o.z = c2 * rstd * (1.0f + scv.z) + shv.z;
    o.w = c3 * rstd * (1.0f + scv.w) + shv.w;
    uint2 vh, vl;
    vh.x = packbf(o.x, o.y); vh.y = packbf(o.z, o.w);
    vl.x = packbf(lobf(o.x), lobf(o.y)); vl.y = packbf(lobf(o.z), lobf(o.w));
    *(uint2*)(Yh + (size_t)row * Cc + c) = vh;
    *(uint2*)(Yl + (size_t)row * Cc + c) = vl;
}

// --------------------------- mma.sync GEMM ---------------------------------
// A, B pre-split bf16 planes [M][K]/[N][K]. Tile 128x128x32, 8 warps,
// 3-stage cp.async pipeline. MMA issued term-outer (hh, lh, hl) so
// consecutive MMAs hit different accumulators (no RAW chains).
// mode 0: Cf = D + bias (+res)   mode 1: gelu->planes   mode 2: ->planes
#define PL_AH 0
#define PL_AL 8192
#define PL_BH 16384
#define PL_BL 24576
#define MSTAGE 32768
#define MM_SMEM (3 * MSTAGE)
#define MBK 32

__global__ __launch_bounds__(256) void mm_gemm(
    const __nv_bfloat16* __restrict__ Ahp, const __nv_bfloat16* __restrict__ Alp,
    const __nv_bfloat16* __restrict__ Bhp, const __nv_bfloat16* __restrict__ Blp,
    const float* __restrict__ bias, const float* __restrict__ res,
    float* __restrict__ Cf, __nv_bfloat16* __restrict__ Ch,
    __nv_bfloat16* __restrict__ Cl, int N, int K, int mode)
{
    extern __shared__ char smem[];
    uint32_t sb = smem_u32(smem);
    const int tid = threadIdx.x, lane = tid & 31, warp = tid >> 5;
    const int wm = warp >> 2, wn = warp & 3;
    const int row0 = blockIdx.y * 128, col0 = blockIdx.x * 128;

    const int lr_ = tid >> 1;
    const int cb_ = (tid & 1) * 2;
    const __nv_bfloat16* Agh = Ahp + (size_t)(row0 + lr_) * K + cb_ * 8;
    const __nv_bfloat16* Agl = Alp + (size_t)(row0 + lr_) * K + cb_ * 8;
    const __nv_bfloat16* Bgh = Bhp + (size_t)(col0 + lr_) * K + cb_ * 8;
    const __nv_bfloat16* Bgl = Blp + (size_t)(col0 + lr_) * K + cb_ * 8;
    const uint32_t sA0 = toff(lr_, cb_), sA1 = toff(lr_, cb_ + 1);

    float d[4][4][4];
    #pragma unroll
    for (int i = 0; i < 4; i++)
        #pragma unroll
        for (int j = 0; j < 4; j++)
            d[i][j][0] = d[i][j][1] = d[i][j][2] = d[i][j][3] = 0.f;

    const int nk = K / MBK;

    #define MM_ISSUE(kt, stg) do {                                   \
        uint32_t bse = sb + (stg) * MSTAGE;                          \
        const __nv_bfloat16* p_;                                     \
        p_ = Agh + (kt) * MBK;                                       \
        cp16(bse + PL_AH + sA0, p_); cp16(bse + PL_AH + sA1, p_ + 8);\
        p_ = Agl + (kt) * MBK;                                       \
        cp16(bse + PL_AL + sA0, p_); cp16(bse + PL_AL + sA1, p_ + 8);\
        p_ = Bgh + (kt) * MBK;                                       \
        cp16(bse + PL_BH + sA0, p_); cp16(bse + PL_BH + sA1, p_ + 8);\
        p_ = Bgl + (kt) * MBK;                                       \
        cp16(bse + PL_BL + sA0, p_); cp16(bse + PL_BL + sA1, p_ + 8);\
        CP_COMMIT;                                                   \
    } while (0)

    MM_ISSUE(0, 0);
    if (nk > 1) MM_ISSUE(1, 1);

    const int g = lane >> 3, lq = lane & 7;

    for (int kt = 0; kt < nk; kt++) {
        if (kt + 1 < nk) { CP_WAIT1; } else { CP_WAIT0; }
        __syncthreads();
        if (kt + 2 < nk) {
            int stg2 = (kt + 2) % 3;
            MM_ISSUE(kt + 2, stg2);
        }
        const uint32_t base = sb + (kt % 3) * MSTAGE;

        #pragma unroll
        for (int ks = 0; ks < 2; ks++) {
            uint32_t ah[4][4], al[4][4], bh[4][2], bl[4][2];
            const int arow = ((g & 1) << 3) + lq;
            const int acol = 2 * ks + (g >> 1);
            #pragma unroll
            for (int mi = 0; mi < 4; mi++) {
                uint32_t o = toff(wm * 64 + mi * 16 + arow, acol);
                ldsm_x4(ah[mi][0], ah[mi][1], ah[mi][2], ah[mi][3], base + PL_AH + o);
                ldsm_x4(al[mi][0], al[mi][1], al[mi][2], al[mi][3], base + PL_AL + o);
            }
            const int brow = ((g >> 1) << 3) + lq;
            const int bcol = 2 * ks + (g & 1);
            #pragma unroll
            for (int nh = 0; nh < 2; nh++) {
                uint32_t o = toff(wn * 32 + nh * 16 + brow, bcol);
                uint32_t t0, t1, t2, t3;
                ldsm_x4(t0, t1, t2, t3, base + PL_BH + o);
                bh[nh*2][0] = t0; bh[nh*2][1] = t1;
                bh[nh*2+1][0] = t2; bh[nh*2+1][1] = t3;
                ldsm_x4(t0, t1, t2, t3, base + PL_BL + o);
                bl[nh*2][0] = t0; bl[nh*2][1] = t1;
                bl[nh*2+1][0] = t2; bl[nh*2+1][1] = t3;
            }
            // term-outer: consecutive MMAs use distinct accumulators
            #pragma unroll
            for (int mi = 0; mi < 4; mi++)
                #pragma unroll
                for (int ni = 0; ni < 4; ni++)
                    mma16816(d[mi][ni], ah[mi], bh[ni]);
            #pragma unroll
            for (int mi = 0; mi < 4; mi++)
                #pragma unroll
                for (int ni = 0; ni < 4; ni++)
                    mma16816(d[mi][ni], al[mi], bh[ni]);
            #pragma unroll
            for (int mi = 0; mi < 4; mi++)
                #pragma unroll
                for (int ni = 0; ni < 4; ni++)
                    mma16816(d[mi][ni], ah[mi], bl[ni]);
        }
    }

    // ---- epilogue (bias cached in regs) ----
    const int rr = lane >> 2, cc2 = (lane & 3) * 2;
    float bch[4][2];
    #pragma unroll
    for (int ni = 0; ni < 4; ni++) {
        int cg = col0 + wn * 32 + ni * 8 + cc2;
        bch[ni][0] = bias[cg]; bch[ni][1] = bias[cg + 1];
    }
    #pragma unroll
    for (int mi = 0; mi < 4; mi++) {
        #pragma unroll
        for (int ni = 0; ni < 4; ni++) {
            int r0g = row0 + wm * 64 + mi * 16 + rr;
            int cg  = col0 + wn * 32 + ni * 8 + cc2;
            #pragma unroll
            for (int hrow = 0; hrow < 2; hrow++) {
                int r = r0g + hrow * 8;
                float v0 = d[mi][ni][hrow * 2 + 0] + bch[ni][0];
                float v1 = d[mi][ni][hrow * 2 + 1] + bch[ni][1];
                if (mode == 0) {
                    if (res) {
                        float2 rv = *(const float2*)(res + (size_t)r * N + cg);
                        v0 += rv.x; v1 += rv.y;
                    }
                    float2 o; o.x = v0; o.y = v1;
                    *(float2*)(Cf + (size_t)r * N + cg) = o;
                } else {
                    if (mode == 1) { v0 = gelu_tanh(v0); v1 = gelu_tanh(v1); }
                    *(uint32_t*)(Ch + (size_t)r * N + cg) = packbf(v0, v1);
                    *(uint32_t*)(Cl + (size_t)r * N + cg) = packbf(lobf(v0), lobf(v1));
                }
            }
        }
    }
}

// ------------------- tensor-core flash attention ---------------------------
// 4 warps, 64 q x 64 k tiles, D=64. All inputs pre-split bf16 planes.
#define AT_QH 0
#define AT_QL 8192
#define AT_KH 16384
#define AT_KL 24576
#define AT_VH 32768
#define AT_VL 40960
#define AT_MD 49152
#define AT_SMEM 49408

__global__ __launch_bounds__(128) void attn_tc(
    const __nv_bfloat16* __restrict__ Qh, const __nv_bfloat16* __restrict__ Ql,
    const __nv_bfloat16* __restrict__ Kh, const __nv_bfloat16* __restrict__ Kl,
    const __nv_bfloat16* __restrict__ Vh, const __nv_bfloat16* __restrict__ Vl,
    __nv_bfloat16* __restrict__ Oh, __nv_bfloat16* __restrict__ Ol,
    const int* __restrict__ maskp,
    int qStride, int kvStride, int Lk, float scale)
{
    extern __shared__ char smem[];
    uint32_t sb = smem_u32(smem);
    const int tid = threadIdx.x, lane = tid & 31, warp = tid >> 5;
    const int b = blockIdx.z, h = blockIdx.y, n0 = blockIdx.x * 64;
    const int w16 = warp * 16;

    #pragma unroll
    for (int it = 0; it < 4; it++) {
        int cid = tid + it * 128;
        int r = cid >> 3, c = cid & 7;
        size_t gq = (size_t)(b * Nn + n0 + r) * qStride + h * Dd + c * 8;
        uint32_t o = aoff(r, c);
        cp16(sb + AT_QH + o, Qh + gq);
        cp16(sb + AT_QL + o, Ql + gq);
    }
    CP_COMMIT; CP_WAIT0;
    __syncthreads();

    uint32_t qh[4][4], ql[4][4];
    {
        int rr = (lane & 7) + 8 * ((lane >> 3) & 1);
        int cc = lane >> 4;
        #pragma unroll
        for (int kc = 0; kc < 4; kc++) {
            uint32_t o = aoff(w16 + rr, kc * 2 + cc);
            ldsm_x4(qh[kc][0], qh[kc][1], qh[kc][2], qh[kc][3], sb + AT_QH + o);
            ldsm_x4(ql[kc][0], ql[kc][1], ql[kc][2], ql[kc][3], sb + AT_QL + o);
        }
    }

    float o_[8][4];
    #pragma unroll
    for (int i = 0; i < 8; i++) { o_[i][0]=o_[i][1]=o_[i][2]=o_[i][3]=0.f; }
    float m0 = -INFINITY, m1 = -INFINITY, l0 = 0.f, l1 = 0.f;

    const int krow = (lane & 7) + 8 * (lane >> 4);
    const int kcsel = (lane >> 3) & 1;
    const int vrow = lane & 15, vcsel = lane >> 4;
    const float* madd = (const float*)(smem + AT_MD);

    const int nTiles = Lk >> 6;
    for (int kt = 0; kt < nTiles; kt++) {
        __syncthreads();
        #pragma unroll
        for (int it = 0; it < 4; it++) {
            int cid = tid + it * 128;
            int r = cid >> 3, c = cid & 7;
            size_t gk = (size_t)(b * Lk + kt * 64 + r) * kvStride + h * Dd + c * 8;
            uint32_t o = aoff(r, c);
            cp16(sb + AT_KH + o, Kh + gk);
            cp16(sb + AT_KL + o, Kl + gk);
            cp16(sb + AT_VH + o, Vh + gk);
            cp16(sb + AT_VL + o, Vl + gk);
        }
        if (maskp && tid < 64)
            ((float*)(smem + AT_MD))[tid] =
                maskp[b * Lk + kt * 64 + tid] ? 0.f : -1e30f;
        CP_COMMIT; CP_WAIT0;
        __syncthreads();

        float s[8][4];
        #pragma unroll
        for (int i = 0; i < 8; i++) { s[i][0]=s[i][1]=s[i][2]=s[i][3]=0.f; }
        #pragma unroll
        for (int kc = 0; kc < 4; kc++) {
            #pragma unroll
            for (int np = 0; np < 4; np++) {
                uint32_t o = aoff(np * 16 + krow, kc * 2 + kcsel);
                uint32_t h0, h1, h2, h3, e0, e1, e2, e3;
                ldsm_x4(h0, h1, h2, h3, sb + AT_KH + o);
                ldsm_x4(e0, e1, e2, e3, sb + AT_KL + o);
                uint32_t bhA[2] = {h0, h1}, bhB[2] = {h2, h3};
                uint32_t blA[2] = {e0, e1}, blB[2] = {e2, e3};
                // interleave terms across the two accumulators
                mma16816(s[np*2],   qh[kc], bhA);
                mma16816(s[np*2+1], qh[kc], bhB);
                mma16816(s[np*2],   ql[kc], bhA);
                mma16816(s[np*2+1], ql[kc], bhB);
                mma16816(s[np*2],   qh[kc], blA);
                mma16816(s[np*2+1], qh[kc], blB);
            }
        }
        #pragma unroll
        for (int nt = 0; nt < 8; nt++) {
            s[nt][0] *= scale; s[nt][1] *= scale;
            s[nt][2] *= scale; s[nt][3] *= scale;
        }
        if (maskp) {
            int cbase = 2 * (lane & 3);
            #pragma unroll
            for (int nt = 0; nt < 8; nt++) {
                float mA = madd[nt * 8 + cbase], mB = madd[nt * 8 + cbase + 1];
                s[nt][0] += mA; s[nt][1] += mB;
                s[nt][2] += mA; s[nt][3] += mB;
            }
        }
        float lm0 = -INFINITY, lm1 = -INFINITY;
        #pragma unroll
        for (int nt = 0; nt < 8; nt++) {
            lm0 = fmaxf(lm0, fmaxf(s[nt][0], s[nt][1]));
            lm1 = fmaxf(lm1, fmaxf(s[nt][2], s[nt][3]));
        }
        lm0 = fmaxf(lm0, __shfl_xor_sync(0xffffffffu, lm0, 1));
        lm0 = fmaxf(lm0, __shfl_xor_sync(0xffffffffu, lm0, 2));
        lm1 = fmaxf(lm1, __shfl_xor_sync(0xffffffffu, lm1, 1));
        lm1 = fmaxf(lm1, __shfl_xor_sync(0xffffffffu, lm1, 2));
        float mn0 = fmaxf(m0, lm0), mn1 = fmaxf(m1, lm1);
        float cr0 = __expf(m0 - mn0), cr1 = __expf(m1 - mn1);
        float sum0 = 0.f, sum1 = 0.f;
        #pragma unroll
        for (int nt = 0; nt < 8; nt++) {
            s[nt][0] = __expf(s[nt][0] - mn0); sum0 += s[nt][0];
            s[nt][1] = __expf(s[nt][1] - mn0); sum0 += s[nt][1];
            s[nt][2] = __expf(s[nt][2] - mn1); sum1 += s[nt][2];
            s[nt][3] = __expf(s[nt][3] - mn1); sum1 += s[nt][3];
        }
        sum0 += __shfl_xor_sync(0xffffffffu, sum0, 1);
        sum0 += __shfl_xor_sync(0xffffffffu, sum0, 2);
        sum1 += __shfl_xor_sync(0xffffffffu, sum1, 1);
        sum1 += __shfl_xor_sync(0xffffffffu, sum1, 2);
        l0 = l0 * cr0 + sum0; l1 = l1 * cr1 + sum1;
        m0 = mn0; m1 = mn1;
        #pragma unroll
        for (int nt = 0; nt < 8; nt++) {
            o_[nt][0] *= cr0; o_[nt][1] *= cr0;
            o_[nt][2] *= cr1; o_[nt][3] *= cr1;
        }
        #pragma unroll
        for (int kc = 0; kc < 4; kc++) {
            uint32_t pah[4], pal[4];
            float* sA = s[kc * 2];
            float* sB = s[kc * 2 + 1];
            pah[0] = packbf(sA[0], sA[1]); pah[1] = packbf(sA[2], sA[3]);
            pah[2] = packbf(sB[0], sB[1]); pah[3] = packbf(sB[2], sB[3]);
            pal[0] = packbf(lobf(sA[0]), lobf(sA[1]));
            pal[1] = packbf(lobf(sA[2]), lobf(sA[3]));
            pal[2] = packbf(lobf(sB[0]), lobf(sB[1]));
            pal[3] = packbf(lobf(sB[2]), lobf(sB[3]));
            #pragma unroll
            for (int dp = 0; dp < 4; dp++) {
                uint32_t o = aoff(kc * 16 + vrow, dp * 2 + vcsel);
                uint32_t v0, v1, v2, v3, u0, u1, u2, u3;
                ldsm_x4t(v0, v1, v2, v3, sb + AT_VH + o);
                ldsm_x4t(u0, u1, u2, u3, sb + AT_VL + o);
                uint32_t bhA[2] = {v0, v1}, bhB[2] = {v2, v3};
                uint32_t blA[2] = {u0, u1}, blB[2] = {u2, u3};
                mma16816(o_[dp*2],   pah, bhA);
                mma16816(o_[dp*2+1], pah, bhB);
                mma16816(o_[dp*2],   pal, bhA);
                mma16816(o_[dp*2+1], pal, bhB);
                mma16816(o_[dp*2],   pah, blA);
                mma16816(o_[dp*2+1], pah, blB);
            }
        }
    }

    float inv0 = 1.0f / l0, inv1 = 1.0f / l1;
    int r0 = w16 + (lane >> 2);
    int cg = h * Dd + 2 * (lane & 3);
    size_t rb = (size_t)(b * Nn + n0);
    #pragma unroll
    for (int nt = 0; nt < 8; nt++) {
        float v0 = o_[nt][0] * inv0, v1 = o_[nt][1] * inv0;
        float w0 = o_[nt][2] * inv1, w1 = o_[nt][3] * inv1;
        size_t o0 = (rb + r0) * Cc + cg + nt * 8;
        size_t o1 = (rb + r0 + 8) * Cc + cg + nt * 8;
        *(uint32_t*)(Oh + o0) = packbf(v0, v1);
        *(uint32_t*)(Ol + o0) = packbf(lobf(v0), lobf(v1));
        *(uint32_t*)(Oh + o1) = packbf(w0, w1);
        *(uint32_t*)(Ol + o1) = packbf(lobf(w0), lobf(w1));
    }
}

// ------------------------------- launch ------------------------------------
static void* sym_addr(const void* sym) {
    void* p = nullptr;
    cudaGetSymbolAddress(&p, sym);
    return p;
}

extern "C" void kernel_launch(void* const* d_in, const int* in_sizes, int n_in,
                              void* d_out, int out_size)
{
    const float* x        = (const float*)d_in[0];
    const float* c_dino   = (const float*)d_in[1];
    const float* c_text   = (const float*)d_in[2];
    const int*   mask     = (const int*)  d_in[3];
    const float* W_ada    = (const float*)d_in[4];
    const float* b_ada    = (const float*)d_in[5];
    const float* W_qkv    = (const float*)d_in[6];
    const float* b_qkv    = (const float*)d_in[7];
    const float* W_psa    = (const float*)d_in[8];
    const float* b_psa    = (const float*)d_in[9];
    const float* W_q      = (const float*)d_in[10];
    const float* b_q      = (const float*)d_in[11];
    const float* W_kv     = (const float*)d_in[12];
    const float* b_kv     = (const float*)d_in[13];
    const float* W_pca    = (const float*)d_in[14];
    const float* b_pca    = (const float*)d_in[15];
    const float* W_fc1    = (const float*)d_in[16];
    const float* b_fc1    = (const float*)d_in[17];
    const float* W_fc2    = (const float*)d_in[18];
    const float* b_fc2    = (const float*)d_in[19];
    float* out = (float*)d_out;

    float* ada  = (float*)sym_addr(g_ada);
    float* x1   = (float*)sym_addr(g_x1);
    float* x2   = (float*)sym_addr(g_x2);

    __nv_bfloat16* hh   = (__nv_bfloat16*)sym_addr(g_hh);
    __nv_bfloat16* hl   = (__nv_bfloat16*)sym_addr(g_hl);
    __nv_bfloat16* qkvh = (__nv_bfloat16*)sym_addr(g_qkvh);
    __nv_bfloat16* qkvl = (__nv_bfloat16*)sym_addr(g_qkvl);
    __nv_bfloat16* kvh  = (__nv_bfloat16*)sym_addr(g_kvh);
    __nv_bfloat16* kvl  = (__nv_bfloat16*)sym_addr(g_kvl);
    __nv_bfloat16* cth  = (__nv_bfloat16*)sym_addr(g_cth);
    __nv_bfloat16* ctl  = (__nv_bfloat16*)sym_addr(g_ctl);
    __nv_bfloat16* ath  = (__nv_bfloat16*)sym_addr(g_ath);
    __nv_bfloat16* atl  = (__nv_bfloat16*)sym_addr(g_atl);
    __nv_bfloat16* mlph = (__nv_bfloat16*)sym_addr(g_mlph);
    __nv_bfloat16* mlpl = (__nv_bfloat16*)sym_addr(g_mlpl);

    __nv_bfloat16* wqkv_h = (__nv_bfloat16*)sym_addr(g_wqkv_h);
    __nv_bfloat16* wqkv_l = (__nv_bfloat16*)sym_addr(g_wqkv_l);
    __nv_bfloat16* wpsa_h = (__nv_bfloat16*)sym_addr(g_wpsa_h);
    __nv_bfloat16* wpsa_l = (__nv_bfloat16*)sym_addr(g_wpsa_l);
    __nv_bfloat16* wq_h   = (__nv_bfloat16*)sym_addr(g_wq_h);
    __nv_bfloat16* wq_l   = (__nv_bfloat16*)sym_addr(g_wq_l);
    __nv_bfloat16* wkv_h  = (__nv_bfloat16*)sym_addr(g_wkv_h);
    __nv_bfloat16* wkv_l  = (__nv_bfloat16*)sym_addr(g_wkv_l);
    __nv_bfloat16* wpca_h = (__nv_bfloat16*)sym_addr(g_wpca_h);
    __nv_bfloat16* wpca_l = (__nv_bfloat16*)sym_addr(g_wpca_l);
    __nv_bfloat16* wfc1_h = (__nv_bfloat16*)sym_addr(g_wfc1_h);
    __nv_bfloat16* wfc1_l = (__nv_bfloat16*)sym_addr(g_wfc1_l);
    __nv_bfloat16* wfc2_h = (__nv_bfloat16*)sym_addr(g_wfc2_h);
    __nv_bfloat16* wfc2_l = (__nv_bfloat16*)sym_addr(g_wfc2_l);

    cudaFuncSetAttribute(attn_tc, cudaFuncAttributeMaxDynamicSharedMemorySize, AT_SMEM);
    cudaFuncSetAttribute(mm_gemm, cudaFuncAttributeMaxDynamicSharedMemorySize, MM_SMEM);

    // ---- weight prep ----
    wprep_kernel<<<dim3(3*Cc/32, Cc/32), 256>>>(W_qkv, wqkv_h, wqkv_l, Cc, 3*Cc);
    wprep_kernel<<<dim3(Cc/32,   Cc/32), 256>>>(W_psa, wpsa_h, wpsa_l, Cc, Cc);
    wprep_kernel<<<dim3(Cc/32,   Cc/32), 256>>>(W_q,   wq_h,   wq_l,   Cc, Cc);
    wprep_kernel<<<dim3(2*Cc/32, Cc/32), 256>>>(W_kv,  wkv_h,  wkv_l,  Cc, 2*Cc);
    wprep_kernel<<<dim3(Cc/32,   Cc/32), 256>>>(W_pca, wpca_h, wpca_l, Cc, Cc);
    wprep_kernel<<<dim3(MLPD/32, Cc/32), 256>>>(W_fc1, wfc1_h, wfc1_l, Cc, MLPD);
    wprep_kernel<<<dim3(Cc/32, MLPD/32), 256>>>(W_fc2, wfc2_h, wfc2_l, MLPD, Cc);

    ada_kernel<<<dim3(24, Bc), 256>>>(c_dino, W_ada, b_ada, ada);
    ct_split_kernel<<<(Bc*Mm*Cc)/1024, 256>>>(c_text, cth, ctl);

    // ---- self attention ----
    lnmod_kernel<<<ROWS, 256>>>(x, ada, 0, hh, hl);
    mm_gemm<<<dim3(3*Cc/128, ROWS/128), 256, MM_SMEM>>>(
        hh, hl, wqkv_h, wqkv_l, b_qkv, nullptr, nullptr, qkvh, qkvl, 3*Cc, Cc, 2);
    attn_tc<<<dim3(Nn/64, Hh, Bc), 128, AT_SMEM>>>(
        qkvh, qkvl, qkvh + Cc, qkvl + Cc, qkvh + 2*Cc, qkvl + 2*Cc,
        ath, atl, nullptr, 3*Cc, 3*Cc, Nn, 0.125f);
    mm_gemm<<<dim3(Cc/128, ROWS/128), 256, MM_SMEM>>>(
        ath, atl, wpsa_h, wpsa_l, b_psa, x, x1, nullptr, nullptr, Cc, Cc, 0);

    // ---- cross attention ----
    lnmod_kernel<<<ROWS, 256>>>(x1, ada, 2*Cc, hh, hl);
    mm_gemm<<<dim3(Cc/128, ROWS/128), 256, MM_SMEM>>>(
        hh, hl, wq_h, wq_l, b_q, nullptr, nullptr, qkvh, qkvl, Cc, Cc, 2);
    mm_gemm<<<dim3(2*Cc/128, (Bc*Mm)/128), 256, MM_SMEM>>>(
        cth, ctl, wkv_h, wkv_l, b_kv, nullptr, nullptr, kvh, kvl, 2*Cc, Cc, 2);
    attn_tc<<<dim3(Nn/64, Hh, Bc), 128, AT_SMEM>>>(
        qkvh, qkvl, kvh, kvl, kvh + Cc, kvl + Cc,
        ath, atl, mask, Cc, 2*Cc, Mm, 0.125f);
    mm_gemm<<<dim3(Cc/128, ROWS/128), 256, MM_SMEM>>>(
        ath, atl, wpca_h, wpca_l, b_pca, x1, x2, nullptr, nullptr, Cc, Cc, 0);

    // ---- MLP ----
    lnmod_kernel<<<ROWS, 256>>>(x2, ada, 4*Cc, hh, hl);
    mm_gemm<<<dim3(MLPD/128, ROWS/128), 256, MM_SMEM>>>(
        hh, hl, wfc1_h, wfc1_l, b_fc1, nullptr, nullptr, mlph, mlpl, MLPD, Cc, 1);
    mm_gemm<<<dim3(Cc/128, ROWS/128), 256, MM_SMEM>>>(
        mlph, mlpl, wfc2_h, wfc2_l, b_fc2, x2, out, nullptr, nullptr, Cc, MLPD, 0);
}

// round 9
// speedup vs baseline: 1.2234x; 1.1503x over previous
#include <cuda_runtime.h>
#include <cuda_fp16.h>
#include <math.h>
#include <stdint.h>

// ---------------------------------------------------------------------------
// DiT block. fp16-split planes: activations 2 planes (hi/lo, ~22 bits),
// weights 1 plane (fp16). GEMM mainloop = 2 MMAs per k16 (Ah*Bh + Al*Bh);
// attention keeps 3-term fp16. Pure cp.async + ldmatrix + mma.sync, fp32 acc.
// B=8, N=1024, M=128, C=1024, H=16, D=64, MLP=4096
// ---------------------------------------------------------------------------

#define Bc  8
#define Nn  1024
#define Mm  128
#define Cc  1024
#define Hh  16
#define Dd  64
#define MLPD 4096
#define ROWS (Bc * Nn)          // 8192

// ------------------------- scratch (device globals) ------------------------
__device__ float g_ada[Bc * 6 * Cc];
__device__ float g_x1[ROWS * Cc];
__device__ float g_x2[ROWS * Cc];

// activation planes (fp16 hi/lo)
__device__ __align__(16) __half g_hh[ROWS * Cc],   g_hl[ROWS * Cc];
__device__ __align__(16) __half g_qkvh[ROWS*3*Cc], g_qkvl[ROWS*3*Cc];
__device__ __align__(16) __half g_kvh[Bc*Mm*2*Cc], g_kvl[Bc*Mm*2*Cc];
__device__ __align__(16) __half g_cth[Bc*Mm*Cc],   g_ctl[Bc*Mm*Cc];
__device__ __align__(16) __half g_ath[ROWS * Cc],  g_atl[ROWS * Cc];
__device__ __align__(16) __half g_mlph[ROWS*MLPD], g_mlpl[ROWS*MLPD];

// transposed fp16 weights: [N][K], single plane
__device__ __align__(16) __half g_wqkv[Cc * 3 * Cc];
__device__ __align__(16) __half g_wpsa[Cc * Cc];
__device__ __align__(16) __half g_wq[Cc * Cc];
__device__ __align__(16) __half g_wkv[Cc * 2 * Cc];
__device__ __align__(16) __half g_wpca[Cc * Cc];
__device__ __align__(16) __half g_wfc1[Cc * MLPD];
__device__ __align__(16) __half g_wfc2[MLPD * Cc];

// ------------------------------ ptx helpers --------------------------------
__device__ __forceinline__ uint32_t smem_u32(const void* p) {
    uint32_t a;
    asm("{ .reg .u64 t; cvta.to.shared.u64 t, %1; cvt.u32.u64 %0, t; }" : "=r"(a) : "l"(p));
    return a;
}
__device__ __forceinline__ void ldsm_x4(uint32_t& r0, uint32_t& r1, uint32_t& r2,
                                        uint32_t& r3, uint32_t a) {
    asm volatile("ldmatrix.sync.aligned.m8n8.x4.shared.b16 {%0,%1,%2,%3}, [%4];"
                 : "=r"(r0), "=r"(r1), "=r"(r2), "=r"(r3) : "r"(a));
}
__device__ __forceinline__ void ldsm_x4t(uint32_t& r0, uint32_t& r1, uint32_t& r2,
                                         uint32_t& r3, uint32_t a) {
    asm volatile("ldmatrix.sync.aligned.m8n8.x4.trans.shared.b16 {%0,%1,%2,%3}, [%4];"
                 : "=r"(r0), "=r"(r1), "=r"(r2), "=r"(r3) : "r"(a));
}
__device__ __forceinline__ void mma16816(float* d, const uint32_t* a, const uint32_t* b) {
    asm volatile(
        "mma.sync.aligned.m16n8k16.row.col.f32.f16.f16.f32 "
        "{%0,%1,%2,%3}, {%4,%5,%6,%7}, {%8,%9}, {%0,%1,%2,%3};"
        : "+f"(d[0]), "+f"(d[1]), "+f"(d[2]), "+f"(d[3])
        : "r"(a[0]), "r"(a[1]), "r"(a[2]), "r"(a[3]), "r"(b[0]), "r"(b[1]));
}
__device__ __forceinline__ void cp16(uint32_t dst, const void* src) {
    asm volatile("cp.async.cg.shared.global [%0], [%1], 16;" :: "r"(dst), "l"(src));
}
#define CP_COMMIT asm volatile("cp.async.commit_group;" ::: "memory")
#define CP_WAIT0  asm volatile("cp.async.wait_group 0;" ::: "memory")
#define CP_WAIT1  asm volatile("cp.async.wait_group 1;" ::: "memory")

// GEMM tile swizzle: 64B rows (4 chunks of 16B)
__device__ __forceinline__ uint32_t toff(int r, int c) {
    return ((uint32_t)r << 6) + ((uint32_t)((c ^ (r >> 1)) & 3) << 4);
}
// attention tile swizzle: 128B rows (8 chunks of 16B)
__device__ __forceinline__ uint32_t aoff(int r, int c) {
    return ((uint32_t)r << 7) + ((uint32_t)((c ^ (r & 7)) & 7) << 4);
}

// ------------------------------ misc helpers -------------------------------
__device__ __forceinline__ float gelu_tanh(float x) {
    float x3 = x * x * x;
    return 0.5f * x * (1.0f + tanhf(0.7978845608028654f * (x + 0.044715f * x3)));
}
__device__ __forceinline__ float block_sum_1024(float v) {
    __shared__ float red[8];
    __shared__ float bcast;
    int lane = threadIdx.x & 31, wid = threadIdx.x >> 5;
    #pragma unroll
    for (int o = 16; o; o >>= 1) v += __shfl_xor_sync(0xffffffffu, v, o);
    __syncthreads();
    if (lane == 0) red[wid] = v;
    __syncthreads();
    if (threadIdx.x == 0) {
        float t = 0.f;
        #pragma unroll
        for (int i = 0; i < 8; i++) t += red[i];
        bcast = t;
    }
    __syncthreads();
    return bcast;
}
__device__ __forceinline__ uint32_t packhf(float x, float y) {
    __half2 p = __floats2half2_rn(x, y);
    return *(uint32_t*)&p;
}
__device__ __forceinline__ float lohf(float x) {
    return x - __half2float(__float2half_rn(x));
}

// -------------------- weight prep: W[K][N] -> Wt fp16 [N][K] ----------------
__global__ __launch_bounds__(256) void wprep_kernel(
    const float* __restrict__ W, __half* __restrict__ Th, int K, int N)
{
    __shared__ float t[32][33];
    int n0 = blockIdx.x * 32, k0 = blockIdx.y * 32;
    int tx = threadIdx.x & 31, ty = threadIdx.x >> 5;
    #pragma unroll
    for (int i = 0; i < 32; i += 8)
        t[ty + i][tx] = W[(size_t)(k0 + ty + i) * N + n0 + tx];
    __syncthreads();
    #pragma unroll
    for (int i = 0; i < 32; i += 8) {
        float v = t[tx][ty + i];
        Th[(size_t)(n0 + ty + i) * K + k0 + tx] = __float2half_rn(v);
    }
}

// ------------------ c_text -> fp16 hi/lo planes ----------------------------
__global__ __launch_bounds__(256) void ct_split_kernel(
    const float* __restrict__ X, __half* __restrict__ Ph, __half* __restrict__ Pl)
{
    size_t i = ((size_t)blockIdx.x * 256 + threadIdx.x) * 4;
    float4 v = *(const float4*)(X + i);
    uint2 vh, vl;
    vh.x = packhf(v.x, v.y); vh.y = packhf(v.z, v.w);
    vl.x = packhf(lohf(v.x), lohf(v.y)); vl.y = packhf(lohf(v.z), lohf(v.w));
    *(uint2*)(Ph + i) = vh;
    *(uint2*)(Pl + i) = vl;
}

// ----------------------- ada = silu(c_dino) @ W_ada + b --------------------
__global__ __launch_bounds__(256) void ada_kernel(
    const float* __restrict__ cdino, const float* __restrict__ W,
    const float* __restrict__ bvec, float* __restrict__ out)
{
    __shared__ float s[Cc];
    int b = blockIdx.y, tid = threadIdx.x;
    for (int i = tid; i < Cc; i += 256) {
        float v = cdino[b * Cc + i];
        s[i] = v / (1.0f + __expf(-v));
    }
    __syncthreads();
    int n = blockIdx.x * 256 + tid;
    float acc = 0.f;
    #pragma unroll 4
    for (int k = 0; k < Cc; k++)
        acc = fmaf(s[k], W[(size_t)k * (6 * Cc) + n], acc);
    out[b * 6 * Cc + n] = acc + bvec[n];
}

// ---------- h = modulate(ln(x), shift, scale) -> fp16 hi/lo planes ---------
__global__ __launch_bounds__(256) void lnmod_kernel(
    const float* __restrict__ X, const float* __restrict__ ada,
    int shiftOff, __half* __restrict__ Yh, __half* __restrict__ Yl)
{
    int row = blockIdx.x;
    int b = row >> 10;
    const float* xr = X + (size_t)row * Cc;
    int c = threadIdx.x * 4;

    float4 v = *(const float4*)(xr + c);
    float mu = block_sum_1024(v.x + v.y + v.z + v.w) * (1.0f / Cc);
    float c0 = v.x - mu, c1 = v.y - mu, c2 = v.z - mu, c3 = v.w - mu;
    float var = block_sum_1024(c0*c0 + c1*c1 + c2*c2 + c3*c3) * (1.0f / Cc);
    float rstd = rsqrtf(var + 1e-6f);

    const float* sh = ada + b * 6 * Cc + shiftOff;
    const float* sc = sh + Cc;
    float4 shv = *(const float4*)(sh + c);
    float4 scv = *(const float4*)(sc + c);
    float4 o;
    o.x = c0 * rstd * (1.0f + scv.x) + shv.x;
    o.y = c1 * rstd * (1.0f + scv.y) + shv.y;
    o.z = c2 * rstd * (1.0f + scv.z) + shv.z;
    o.w = c3 * rstd * (1.0f + scv.w) + shv.w;
    uint2 vh, vl;
    vh.x = packhf(o.x, o.y); vh.y = packhf(o.z, o.w);
    vl.x = packhf(lohf(o.x), lohf(o.y)); vl.y = packhf(lohf(o.z), lohf(o.w));
    *(uint2*)(Yh + (size_t)row * Cc + c) = vh;
    *(uint2*)(Yl + (size_t)row * Cc + c) = vl;
}

// --------------------------- mma.sync GEMM ---------------------------------
// A: fp16 hi/lo planes [M][K]; B: single fp16 plane [N][K].
// Tile 128x128x32, 8 warps (4x2), warp tile 32x64, 3-stage pipeline.
// 2 MMAs per k16: Ah*Bh + Al*Bh.
// mode 0: Cf = D + bias (+res)   mode 1: gelu->planes   mode 2: ->planes
#define PL_AH 0
#define PL_AL 8192
#define PL_BH 16384
#define MSTAGE 24576
#define MM_SMEM (3 * MSTAGE)    // 73728
#define MBK 32

__global__ __launch_bounds__(256) void mm_gemm(
    const __half* __restrict__ Ahp, const __half* __restrict__ Alp,
    const __half* __restrict__ Bhp,
    const float* __restrict__ bias, const float* __restrict__ res,
    float* __restrict__ Cf, __half* __restrict__ Ch,
    __half* __restrict__ Cl, int N, int K, int mode)
{
    extern __shared__ char smem[];
    uint32_t sb = smem_u32(smem);
    const int tid = threadIdx.x, lane = tid & 31, warp = tid >> 5;
    const int wm = warp & 3, wn = warp >> 2;        // 4 x 2 warp grid
    const int row0 = blockIdx.y * 128, col0 = blockIdx.x * 128;

    const int lr_ = tid >> 1;
    const int cb_ = (tid & 1) * 2;
    const __half* Agh = Ahp + (size_t)(row0 + lr_) * K + cb_ * 8;
    const __half* Agl = Alp + (size_t)(row0 + lr_) * K + cb_ * 8;
    const __half* Bgh = Bhp + (size_t)(col0 + lr_) * K + cb_ * 8;
    const uint32_t sA0 = toff(lr_, cb_), sA1 = toff(lr_, cb_ + 1);

    float d[2][8][4];
    #pragma unroll
    for (int i = 0; i < 2; i++)
        #pragma unroll
        for (int j = 0; j < 8; j++)
            d[i][j][0] = d[i][j][1] = d[i][j][2] = d[i][j][3] = 0.f;

    const int nk = K / MBK;

    #define MM_ISSUE(kt, stg) do {                                   \
        uint32_t bse = sb + (stg) * MSTAGE;                          \
        const __half* p_;                                            \
        p_ = Agh + (kt) * MBK;                                       \
        cp16(bse + PL_AH + sA0, p_); cp16(bse + PL_AH + sA1, p_ + 8);\
        p_ = Agl + (kt) * MBK;                                       \
        cp16(bse + PL_AL + sA0, p_); cp16(bse + PL_AL + sA1, p_ + 8);\
        p_ = Bgh + (kt) * MBK;                                       \
        cp16(bse + PL_BH + sA0, p_); cp16(bse + PL_BH + sA1, p_ + 8);\
        CP_COMMIT;                                                   \
    } while (0)

    MM_ISSUE(0, 0);
    if (nk > 1) MM_ISSUE(1, 1);

    const int g = lane >> 3, lq = lane & 7;

    for (int kt = 0; kt < nk; kt++) {
        if (kt + 1 < nk) { CP_WAIT1; } else { CP_WAIT0; }
        __syncthreads();
        if (kt + 2 < nk) {
            int stg2 = (kt + 2) % 3;
            MM_ISSUE(kt + 2, stg2);
        }
        const uint32_t base = sb + (kt % 3) * MSTAGE;

        #pragma unroll
        for (int ks = 0; ks < 2; ks++) {
            uint32_t ah[2][4], al[2][4], bh[8][2];
            const int arow = ((g & 1) << 3) + lq;
            const int acol = 2 * ks + (g >> 1);
            #pragma unroll
            for (int mi = 0; mi < 2; mi++) {
                uint32_t o = toff(wm * 32 + mi * 16 + arow, acol);
                ldsm_x4(ah[mi][0], ah[mi][1], ah[mi][2], ah[mi][3], base + PL_AH + o);
                ldsm_x4(al[mi][0], al[mi][1], al[mi][2], al[mi][3], base + PL_AL + o);
            }
            const int brow = ((g >> 1) << 3) + lq;
            const int bcol = 2 * ks + (g & 1);
            #pragma unroll
            for (int nh = 0; nh < 4; nh++) {
                uint32_t o = toff(wn * 64 + nh * 16 + brow, bcol);
                uint32_t t0, t1, t2, t3;
                ldsm_x4(t0, t1, t2, t3, base + PL_BH + o);
                bh[nh*2][0] = t0; bh[nh*2][1] = t1;
                bh[nh*2+1][0] = t2; bh[nh*2+1][1] = t3;
            }
            #pragma unroll
            for (int mi = 0; mi < 2; mi++)
                #pragma unroll
                for (int ni = 0; ni < 8; ni++)
                    mma16816(d[mi][ni], ah[mi], bh[ni]);
            #pragma unroll
            for (int mi = 0; mi < 2; mi++)
                #pragma unroll
                for (int ni = 0; ni < 8; ni++)
                    mma16816(d[mi][ni], al[mi], bh[ni]);
        }
    }

    // ---- epilogue ----
    const int rr = lane >> 2, cc2 = (lane & 3) * 2;
    float bch[8][2];
    #pragma unroll
    for (int ni = 0; ni < 8; ni++) {
        int cg = col0 + wn * 64 + ni * 8 + cc2;
        bch[ni][0] = bias[cg]; bch[ni][1] = bias[cg + 1];
    }
    #pragma unroll
    for (int mi = 0; mi < 2; mi++) {
        #pragma unroll
        for (int ni = 0; ni < 8; ni++) {
            int r0g = row0 + wm * 32 + mi * 16 + rr;
            int cg  = col0 + wn * 64 + ni * 8 + cc2;
            #pragma unroll
            for (int hrow = 0; hrow < 2; hrow++) {
                int r = r0g + hrow * 8;
                float v0 = d[mi][ni][hrow * 2 + 0] + bch[ni][0];
                float v1 = d[mi][ni][hrow * 2 + 1] + bch[ni][1];
                if (mode == 0) {
                    if (res) {
                        float2 rv = *(const float2*)(res + (size_t)r * N + cg);
                        v0 += rv.x; v1 += rv.y;
                    }
                    float2 o; o.x = v0; o.y = v1;
                    *(float2*)(Cf + (size_t)r * N + cg) = o;
                } else {
                    if (mode == 1) { v0 = gelu_tanh(v0); v1 = gelu_tanh(v1); }
                    *(uint32_t*)(Ch + (size_t)r * N + cg) = packhf(v0, v1);
                    *(uint32_t*)(Cl + (size_t)r * N + cg) = packhf(lohf(v0), lohf(v1));
                }
            }
        }
    }
}

// ------------------- tensor-core flash attention ---------------------------
// 4 warps, 64 q x 64 k tiles, D=64. fp16 hi/lo planes, 3-term split.
#define AT_QH 0
#define AT_QL 8192
#define AT_KH 16384
#define AT_KL 24576
#define AT_VH 32768
#define AT_VL 40960
#define AT_MD 49152
#define AT_SMEM 49408

__global__ __launch_bounds__(128) void attn_tc(
    const __half* __restrict__ Qh, const __half* __restrict__ Ql,
    const __half* __restrict__ Kh, const __half* __restrict__ Kl,
    const __half* __restrict__ Vh, const __half* __restrict__ Vl,
    __half* __restrict__ Oh, __half* __restrict__ Ol,
    const int* __restrict__ maskp,
    int qStride, int kvStride, int Lk, float scale)
{
    extern __shared__ char smem[];
    uint32_t sb = smem_u32(smem);
    const int tid = threadIdx.x, lane = tid & 31, warp = tid >> 5;
    const int b = blockIdx.z, h = blockIdx.y, n0 = blockIdx.x * 64;
    const int w16 = warp * 16;

    #pragma unroll
    for (int it = 0; it < 4; it++) {
        int cid = tid + it * 128;
        int r = cid >> 3, c = cid & 7;
        size_t gq = (size_t)(b * Nn + n0 + r) * qStride + h * Dd + c * 8;
        uint32_t o = aoff(r, c);
        cp16(sb + AT_QH + o, Qh + gq);
        cp16(sb + AT_QL + o, Ql + gq);
    }
    CP_COMMIT; CP_WAIT0;
    __syncthreads();

    uint32_t qh[4][4], ql[4][4];
    {
        int rr = (lane & 7) + 8 * ((lane >> 3) & 1);
        int cc = lane >> 4;
        #pragma unroll
        for (int kc = 0; kc < 4; kc++) {
            uint32_t o = aoff(w16 + rr, kc * 2 + cc);
            ldsm_x4(qh[kc][0], qh[kc][1], qh[kc][2], qh[kc][3], sb + AT_QH + o);
            ldsm_x4(ql[kc][0], ql[kc][1], ql[kc][2], ql[kc][3], sb + AT_QL + o);
        }
    }

    float o_[8][4];
    #pragma unroll
    for (int i = 0; i < 8; i++) { o_[i][0]=o_[i][1]=o_[i][2]=o_[i][3]=0.f; }
    float m0 = -INFINITY, m1 = -INFINITY, l0 = 0.f, l1 = 0.f;

    const int krow = (lane & 7) + 8 * (lane >> 4);
    const int kcsel = (lane >> 3) & 1;
    const int vrow = lane & 15, vcsel = lane >> 4;
    const float* madd = (const float*)(smem + AT_MD);

    const int nTiles = Lk >> 6;
    for (int kt = 0; kt < nTiles; kt++) {
        __syncthreads();
        #pragma unroll
        for (int it = 0; it < 4; it++) {
            int cid = tid + it * 128;
            int r = cid >> 3, c = cid & 7;
            size_t gk = (size_t)(b * Lk + kt * 64 + r) * kvStride + h * Dd + c * 8;
            uint32_t o = aoff(r, c);
            cp16(sb + AT_KH + o, Kh + gk);
            cp16(sb + AT_KL + o, Kl + gk);
            cp16(sb + AT_VH + o, Vh + gk);
            cp16(sb + AT_VL + o, Vl + gk);
        }
        if (maskp && tid < 64)
            ((float*)(smem + AT_MD))[tid] =
                maskp[b * Lk + kt * 64 + tid] ? 0.f : -1e30f;
        CP_COMMIT; CP_WAIT0;
        __syncthreads();

        float s[8][4];
        #pragma unroll
        for (int i = 0; i < 8; i++) { s[i][0]=s[i][1]=s[i][2]=s[i][3]=0.f; }
        #pragma unroll
        for (int kc = 0; kc < 4; kc++) {
            #pragma unroll
            for (int np = 0; np < 4; np++) {
                uint32_t o = aoff(np * 16 + krow, kc * 2 + kcsel);
                uint32_t h0, h1, h2, h3, e0, e1, e2, e3;
                ldsm_x4(h0, h1, h2, h3, sb + AT_KH + o);
                ldsm_x4(e0, e1, e2, e3, sb + AT_KL + o);
                uint32_t bhA[2] = {h0, h1}, bhB[2] = {h2, h3};
                uint32_t blA[2] = {e0, e1}, blB[2] = {e2, e3};
                mma16816(s[np*2],   qh[kc], bhA);
                mma16816(s[np*2+1], qh[kc], bhB);
                mma16816(s[np*2],   ql[kc], bhA);
                mma16816(s[np*2+1], ql[kc], bhB);
                mma16816(s[np*2],   qh[kc], blA);
                mma16816(s[np*2+1], qh[kc], blB);
            }
        }
        #pragma unroll
        for (int nt = 0; nt < 8; nt++) {
            s[nt][0] *= scale; s[nt][1] *= scale;
            s[nt][2] *= scale; s[nt][3] *= scale;
        }
        if (maskp) {
            int cbase = 2 * (lane & 3);
            #pragma unroll
            for (int nt = 0; nt < 8; nt++) {
                float mA = madd[nt * 8 + cbase], mB = madd[nt * 8 + cbase + 1];
                s[nt][0] += mA; s[nt][1] += mB;
                s[nt][2] += mA; s[nt][3] += mB;
            }
        }
        float lm0 = -INFINITY, lm1 = -INFINITY;
        #pragma unroll
        for (int nt = 0; nt < 8; nt++) {
            lm0 = fmaxf(lm0, fmaxf(s[nt][0], s[nt][1]));
            lm1 = fmaxf(lm1, fmaxf(s[nt][2], s[nt][3]));
        }
        lm0 = fmaxf(lm0, __shfl_xor_sync(0xffffffffu, lm0, 1));
        lm0 = fmaxf(lm0, __shfl_xor_sync(0xffffffffu, lm0, 2));
        lm1 = fmaxf(lm1, __shfl_xor_sync(0xffffffffu, lm1, 1));
        lm1 = fmaxf(lm1, __shfl_xor_sync(0xffffffffu, lm1, 2));
        float mn0 = fmaxf(m0, lm0), mn1 = fmaxf(m1, lm1);
        float cr0 = __expf(m0 - mn0), cr1 = __expf(m1 - mn1);
        float sum0 = 0.f, sum1 = 0.f;
        #pragma unroll
        for (int nt = 0; nt < 8; nt++) {
            s[nt][0] = __expf(s[nt][0] - mn0); sum0 += s[nt][0];
            s[nt][1] = __expf(s[nt][1] - mn0); sum0 += s[nt][1];
            s[nt][2] = __expf(s[nt][2] - mn1); sum1 += s[nt][2];
            s[nt][3] = __expf(s[nt][3] - mn1); sum1 += s[nt][3];
        }
        sum0 += __shfl_xor_sync(0xffffffffu, sum0, 1);
        sum0 += __shfl_xor_sync(0xffffffffu, sum0, 2);
        sum1 += __shfl_xor_sync(0xffffffffu, sum1, 1);
        sum1 += __shfl_xor_sync(0xffffffffu, sum1, 2);
        l0 = l0 * cr0 + sum0; l1 = l1 * cr1 + sum1;
        m0 = mn0; m1 = mn1;
        #pragma unroll
        for (int nt = 0; nt < 8; nt++) {
            o_[nt][0] *= cr0; o_[nt][1] *= cr0;
            o_[nt][2] *= cr1; o_[nt][3] *= cr1;
        }
        #pragma unroll
        for (int kc = 0; kc < 4; kc++) {
            uint32_t pah[4], pal[4];
            float* sA = s[kc * 2];
            float* sB = s[kc * 2 + 1];
            pah[0] = packhf(sA[0], sA[1]); pah[1] = packhf(sA[2], sA[3]);
            pah[2] = packhf(sB[0], sB[1]); pah[3] = packhf(sB[2], sB[3]);
            pal[0] = packhf(lohf(sA[0]), lohf(sA[1]));
            pal[1] = packhf(lohf(sA[2]), lohf(sA[3]));
            pal[2] = packhf(lohf(sB[0]), lohf(sB[1]));
            pal[3] = packhf(lohf(sB[2]), lohf(sB[3]));
            #pragma unroll
            for (int dp = 0; dp < 4; dp++) {
                uint32_t o = aoff(kc * 16 + vrow, dp * 2 + vcsel);
                uint32_t v0, v1, v2, v3, u0, u1, u2, u3;
                ldsm_x4t(v0, v1, v2, v3, sb + AT_VH + o);
                ldsm_x4t(u0, u1, u2, u3, sb + AT_VL + o);
                uint32_t bhA[2] = {v0, v1}, bhB[2] = {v2, v3};
                uint32_t blA[2] = {u0, u1}, blB[2] = {u2, u3};
                mma16816(o_[dp*2],   pah, bhA);
                mma16816(o_[dp*2+1], pah, bhB);
                mma16816(o_[dp*2],   pal, bhA);
                mma16816(o_[dp*2+1], pal, bhB);
                mma16816(o_[dp*2],   pah, blA);
                mma16816(o_[dp*2+1], pah, blB);
            }
        }
    }

    float inv0 = 1.0f / l0, inv1 = 1.0f / l1;
    int r0 = w16 + (lane >> 2);
    int cg = h * Dd + 2 * (lane & 3);
    size_t rb = (size_t)(b * Nn + n0);
    #pragma unroll
    for (int nt = 0; nt < 8; nt++) {
        float v0 = o_[nt][0] * inv0, v1 = o_[nt][1] * inv0;
        float w0 = o_[nt][2] * inv1, w1 = o_[nt][3] * inv1;
        size_t o0 = (rb + r0) * Cc + cg + nt * 8;
        size_t o1 = (rb + r0 + 8) * Cc + cg + nt * 8;
        *(uint32_t*)(Oh + o0) = packhf(v0, v1);
        *(uint32_t*)(Ol + o0) = packhf(lohf(v0), lohf(v1));
        *(uint32_t*)(Oh + o1) = packhf(w0, w1);
        *(uint32_t*)(Ol + o1) = packhf(lohf(w0), lohf(w1));
    }
}

// ------------------------------- launch ------------------------------------
static void* sym_addr(const void* sym) {
    void* p = nullptr;
    cudaGetSymbolAddress(&p, sym);
    return p;
}

extern "C" void kernel_launch(void* const* d_in, const int* in_sizes, int n_in,
                              void* d_out, int out_size)
{
    const float* x        = (const float*)d_in[0];
    const float* c_dino   = (const float*)d_in[1];
    const float* c_text   = (const float*)d_in[2];
    const int*   mask     = (const int*)  d_in[3];
    const float* W_ada    = (const float*)d_in[4];
    const float* b_ada    = (const float*)d_in[5];
    const float* W_qkv    = (const float*)d_in[6];
    const float* b_qkv    = (const float*)d_in[7];
    const float* W_psa    = (const float*)d_in[8];
    const float* b_psa    = (const float*)d_in[9];
    const float* W_q      = (const float*)d_in[10];
    const float* b_q      = (const float*)d_in[11];
    const float* W_kv     = (const float*)d_in[12];
    const float* b_kv     = (const float*)d_in[13];
    const float* W_pca    = (const float*)d_in[14];
    const float* b_pca    = (const float*)d_in[15];
    const float* W_fc1    = (const float*)d_in[16];
    const float* b_fc1    = (const float*)d_in[17];
    const float* W_fc2    = (const float*)d_in[18];
    const float* b_fc2    = (const float*)d_in[19];
    float* out = (float*)d_out;

    float* ada  = (float*)sym_addr(g_ada);
    float* x1   = (float*)sym_addr(g_x1);
    float* x2   = (float*)sym_addr(g_x2);

    __half* hh   = (__half*)sym_addr(g_hh);
    __half* hl   = (__half*)sym_addr(g_hl);
    __half* qkvh = (__half*)sym_addr(g_qkvh);
    __half* qkvl = (__half*)sym_addr(g_qkvl);
    __half* kvh  = (__half*)sym_addr(g_kvh);
    __half* kvl  = (__half*)sym_addr(g_kvl);
    __half* cth  = (__half*)sym_addr(g_cth);
    __half* ctl  = (__half*)sym_addr(g_ctl);
    __half* ath  = (__half*)sym_addr(g_ath);
    __half* atl  = (__half*)sym_addr(g_atl);
    __half* mlph = (__half*)sym_addr(g_mlph);
    __half* mlpl = (__half*)sym_addr(g_mlpl);

    __half* wqkv = (__half*)sym_addr(g_wqkv);
    __half* wpsa = (__half*)sym_addr(g_wpsa);
    __half* wq   = (__half*)sym_addr(g_wq);
    __half* wkv  = (__half*)sym_addr(g_wkv);
    __half* wpca = (__half*)sym_addr(g_wpca);
    __half* wfc1 = (__half*)sym_addr(g_wfc1);
    __half* wfc2 = (__half*)sym_addr(g_wfc2);

    cudaFuncSetAttribute(attn_tc, cudaFuncAttributeMaxDynamicSharedMemorySize, AT_SMEM);
    cudaFuncSetAttribute(mm_gemm, cudaFuncAttributeMaxDynamicSharedMemorySize, MM_SMEM);

    // ---- weight prep (transpose, fp16) ----
    wprep_kernel<<<dim3(3*Cc/32, Cc/32), 256>>>(W_qkv, wqkv, Cc, 3*Cc);
    wprep_kernel<<<dim3(Cc/32,   Cc/32), 256>>>(W_psa, wpsa, Cc, Cc);
    wprep_kernel<<<dim3(Cc/32,   Cc/32), 256>>>(W_q,   wq,   Cc, Cc);
    wprep_kernel<<<dim3(2*Cc/32, Cc/32), 256>>>(W_kv,  wkv,  Cc, 2*Cc);
    wprep_kernel<<<dim3(Cc/32,   Cc/32), 256>>>(W_pca, wpca, Cc, Cc);
    wprep_kernel<<<dim3(MLPD/32, Cc/32), 256>>>(W_fc1, wfc1, Cc, MLPD);
    wprep_kernel<<<dim3(Cc/32, MLPD/32), 256>>>(W_fc2, wfc2, MLPD, Cc);

    ada_kernel<<<dim3(24, Bc), 256>>>(c_dino, W_ada, b_ada, ada);
    ct_split_kernel<<<(Bc*Mm*Cc)/1024, 256>>>(c_text, cth, ctl);

    // ---- self attention ----
    lnmod_kernel<<<ROWS, 256>>>(x, ada, 0, hh, hl);
    mm_gemm<<<dim3(3*Cc/128, ROWS/128), 256, MM_SMEM>>>(
        hh, hl, wqkv, b_qkv, nullptr, nullptr, qkvh, qkvl, 3*Cc, Cc, 2);
    attn_tc<<<dim3(Nn/64, Hh, Bc), 128, AT_SMEM>>>(
        qkvh, qkvl, qkvh + Cc, qkvl + Cc, qkvh + 2*Cc, qkvl + 2*Cc,
        ath, atl, nullptr, 3*Cc, 3*Cc, Nn, 0.125f);
    mm_gemm<<<dim3(Cc/128, ROWS/128), 256, MM_SMEM>>>(
        ath, atl, wpsa, b_psa, x, x1, nullptr, nullptr, Cc, Cc, 0);

    // ---- cross attention ----
    lnmod_kernel<<<ROWS, 256>>>(x1, ada, 2*Cc, hh, hl);
    mm_gemm<<<dim3(Cc/128, ROWS/128), 256, MM_SMEM>>>(
        hh, hl, wq, b_q, nullptr, nullptr, qkvh, qkvl, Cc, Cc, 2);
    mm_gemm<<<dim3(2*Cc/128, (Bc*Mm)/128), 256, MM_SMEM>>>(
        cth, ctl, wkv, b_kv, nullptr, nullptr, kvh, kvl, 2*Cc, Cc, 2);
    attn_tc<<<dim3(Nn/64, Hh, Bc), 128, AT_SMEM>>>(
        qkvh, qkvl, kvh, kvl, kvh + Cc, kvl + Cc,
        ath, atl, mask, Cc, 2*Cc, Mm, 0.125f);
    mm_gemm<<<dim3(Cc/128, ROWS/128), 256, MM_SMEM>>>(
        ath, atl, wpca, b_pca, x1, x2, nullptr, nullptr, Cc, Cc, 0);

    // ---- MLP ----
    lnmod_kernel<<<ROWS, 256>>>(x2, ada, 4*Cc, hh, hl);
    mm_gemm<<<dim3(MLPD/128, ROWS/128), 256, MM_SMEM>>>(
        hh, hl, wfc1, b_fc1, nullptr, nullptr, mlph, mlpl, MLPD, Cc, 1);
    mm_gemm<<<dim3(Cc/128, ROWS/128), 256, MM_SMEM>>>(
        mlph, mlpl, wfc2, b_fc2, x2, out, nullptr, nullptr, Cc, MLPD, 0);
}

// round 10
// speedup vs baseline: 1.8552x; 1.5164x over previous
#include <cuda_runtime.h>
#include <cuda_fp16.h>
#include <math.h>
#include <stdint.h>

// ---------------------------------------------------------------------------
// DiT block, pure fp16 tensor-core pipeline (fp32 accumulate everywhere).
// Single fp16 plane for all GEMM/attention operands; validated error model
// puts end-to-end rel_err ~2-3.5e-4 (gate 1e-3).
// B=8, N=1024, M=128, C=1024, H=16, D=64, MLP=4096
// ---------------------------------------------------------------------------

#define Bc  8
#define Nn  1024
#define Mm  128
#define Cc  1024
#define Hh  16
#define Dd  64
#define MLPD 4096
#define ROWS (Bc * Nn)          // 8192

// ------------------------- scratch (device globals) ------------------------
__device__ float g_ada[Bc * 6 * Cc];
__device__ float g_x1[ROWS * Cc];
__device__ float g_x2[ROWS * Cc];

// fp16 activations
__device__ __align__(16) __half g_h[ROWS * Cc];
__device__ __align__(16) __half g_qkv[ROWS * 3 * Cc];
__device__ __align__(16) __half g_kv[Bc * Mm * 2 * Cc];
__device__ __align__(16) __half g_ct[Bc * Mm * Cc];
__device__ __align__(16) __half g_at[ROWS * Cc];
__device__ __align__(16) __half g_mlp[ROWS * MLPD];

// transposed fp16 weights [N][K]
__device__ __align__(16) __half g_wqkv[Cc * 3 * Cc];
__device__ __align__(16) __half g_wpsa[Cc * Cc];
__device__ __align__(16) __half g_wq[Cc * Cc];
__device__ __align__(16) __half g_wkv[Cc * 2 * Cc];
__device__ __align__(16) __half g_wpca[Cc * Cc];
__device__ __align__(16) __half g_wfc1[Cc * MLPD];
__device__ __align__(16) __half g_wfc2[MLPD * Cc];

// ------------------------------ ptx helpers --------------------------------
__device__ __forceinline__ uint32_t smem_u32(const void* p) {
    uint32_t a;
    asm("{ .reg .u64 t; cvta.to.shared.u64 t, %1; cvt.u32.u64 %0, t; }" : "=r"(a) : "l"(p));
    return a;
}
__device__ __forceinline__ void ldsm_x4(uint32_t& r0, uint32_t& r1, uint32_t& r2,
                                        uint32_t& r3, uint32_t a) {
    asm volatile("ldmatrix.sync.aligned.m8n8.x4.shared.b16 {%0,%1,%2,%3}, [%4];"
                 : "=r"(r0), "=r"(r1), "=r"(r2), "=r"(r3) : "r"(a));
}
__device__ __forceinline__ void ldsm_x4t(uint32_t& r0, uint32_t& r1, uint32_t& r2,
                                         uint32_t& r3, uint32_t a) {
    asm volatile("ldmatrix.sync.aligned.m8n8.x4.trans.shared.b16 {%0,%1,%2,%3}, [%4];"
                 : "=r"(r0), "=r"(r1), "=r"(r2), "=r"(r3) : "r"(a));
}
__device__ __forceinline__ void mma16816(float* d, const uint32_t* a, const uint32_t* b) {
    asm volatile(
        "mma.sync.aligned.m16n8k16.row.col.f32.f16.f16.f32 "
        "{%0,%1,%2,%3}, {%4,%5,%6,%7}, {%8,%9}, {%0,%1,%2,%3};"
        : "+f"(d[0]), "+f"(d[1]), "+f"(d[2]), "+f"(d[3])
        : "r"(a[0]), "r"(a[1]), "r"(a[2]), "r"(a[3]), "r"(b[0]), "r"(b[1]));
}
__device__ __forceinline__ void cp16(uint32_t dst, const void* src) {
    asm volatile("cp.async.cg.shared.global [%0], [%1], 16;" :: "r"(dst), "l"(src));
}
#define CP_COMMIT asm volatile("cp.async.commit_group;" ::: "memory")
#define CP_WAIT0  asm volatile("cp.async.wait_group 0;" ::: "memory")
#define CP_WAIT1  asm volatile("cp.async.wait_group 1;" ::: "memory")

// GEMM tile swizzle: 64B rows (4 chunks of 16B)
__device__ __forceinline__ uint32_t toff(int r, int c) {
    return ((uint32_t)r << 6) + ((uint32_t)((c ^ (r >> 1)) & 3) << 4);
}
// attention tile swizzle: 128B rows (8 chunks of 16B)
__device__ __forceinline__ uint32_t aoff(int r, int c) {
    return ((uint32_t)r << 7) + ((uint32_t)((c ^ (r & 7)) & 7) << 4);
}

// ------------------------------ misc helpers -------------------------------
__device__ __forceinline__ float gelu_tanh(float x) {
    float x3 = x * x * x;
    return 0.5f * x * (1.0f + tanhf(0.7978845608028654f * (x + 0.044715f * x3)));
}
__device__ __forceinline__ float block_sum_1024(float v) {
    __shared__ float red[8];
    __shared__ float bcast;
    int lane = threadIdx.x & 31, wid = threadIdx.x >> 5;
    #pragma unroll
    for (int o = 16; o; o >>= 1) v += __shfl_xor_sync(0xffffffffu, v, o);
    __syncthreads();
    if (lane == 0) red[wid] = v;
    __syncthreads();
    if (threadIdx.x == 0) {
        float t = 0.f;
        #pragma unroll
        for (int i = 0; i < 8; i++) t += red[i];
        bcast = t;
    }
    __syncthreads();
    return bcast;
}
__device__ __forceinline__ uint32_t packhf(float x, float y) {
    __half2 p = __floats2half2_rn(x, y);
    return *(uint32_t*)&p;
}

// -------------------- weight prep: W[K][N] -> Wt fp16 [N][K] ----------------
__global__ __launch_bounds__(256) void wprep_kernel(
    const float* __restrict__ W, __half* __restrict__ Th, int K, int N)
{
    __shared__ float t[32][33];
    int n0 = blockIdx.x * 32, k0 = blockIdx.y * 32;
    int tx = threadIdx.x & 31, ty = threadIdx.x >> 5;
    #pragma unroll
    for (int i = 0; i < 32; i += 8)
        t[ty + i][tx] = W[(size_t)(k0 + ty + i) * N + n0 + tx];
    __syncthreads();
    #pragma unroll
    for (int i = 0; i < 32; i += 8)
        Th[(size_t)(n0 + ty + i) * K + k0 + tx] = __float2half_rn(t[tx][ty + i]);
}

// ------------------ c_text -> fp16 ----------------------------------------
__global__ __launch_bounds__(256) void ct_split_kernel(
    const float* __restrict__ X, __half* __restrict__ Ph)
{
    size_t i = ((size_t)blockIdx.x * 256 + threadIdx.x) * 4;
    float4 v = *(const float4*)(X + i);
    uint2 vh;
    vh.x = packhf(v.x, v.y); vh.y = packhf(v.z, v.w);
    *(uint2*)(Ph + i) = vh;
}

// ----------------------- ada = silu(c_dino) @ W_ada + b --------------------
__global__ __launch_bounds__(256) void ada_kernel(
    const float* __restrict__ cdino, const float* __restrict__ W,
    const float* __restrict__ bvec, float* __restrict__ out)
{
    __shared__ float s[Cc];
    int b = blockIdx.y, tid = threadIdx.x;
    for (int i = tid; i < Cc; i += 256) {
        float v = cdino[b * Cc + i];
        s[i] = v / (1.0f + __expf(-v));
    }
    __syncthreads();
    int n = blockIdx.x * 256 + tid;
    float acc = 0.f;
    #pragma unroll 4
    for (int k = 0; k < Cc; k++)
        acc = fmaf(s[k], W[(size_t)k * (6 * Cc) + n], acc);
    out[b * 6 * Cc + n] = acc + bvec[n];
}

// ---------- h = modulate(ln(x), shift, scale) -> fp16 ----------------------
__global__ __launch_bounds__(256) void lnmod_kernel(
    const float* __restrict__ X, const float* __restrict__ ada,
    int shiftOff, __half* __restrict__ Yh)
{
    int row = blockIdx.x;
    int b = row >> 10;
    const float* xr = X + (size_t)row * Cc;
    int c = threadIdx.x * 4;

    float4 v = *(const float4*)(xr + c);
    float mu = block_sum_1024(v.x + v.y + v.z + v.w) * (1.0f / Cc);
    float c0 = v.x - mu, c1 = v.y - mu, c2 = v.z - mu, c3 = v.w - mu;
    float var = block_sum_1024(c0*c0 + c1*c1 + c2*c2 + c3*c3) * (1.0f / Cc);
    float rstd = rsqrtf(var + 1e-6f);

    const float* sh = ada + b * 6 * Cc + shiftOff;
    const float* sc = sh + Cc;
    float4 shv = *(const float4*)(sh + c);
    float4 scv = *(const float4*)(sc + c);
    float4 o;
    o.x = c0 * rstd * (1.0f + scv.x) + shv.x;
    o.y = c1 * rstd * (1.0f + scv.y) + shv.y;
    o.z = c2 * rstd * (1.0f + scv.z) + shv.z;
    o.w = c3 * rstd * (1.0f + scv.w) + shv.w;
    uint2 vh;
    vh.x = packhf(o.x, o.y); vh.y = packhf(o.z, o.w);
    *(uint2*)(Yh + (size_t)row * Cc + c) = vh;
}

// --------------------------- mma.sync GEMM ---------------------------------
// A fp16 [M][K]; B fp16 [N][K]. Tile 128x128x32, 8 warps (4x2),
// warp tile 32x64, 3-stage pipeline, 1 MMA per k16.
// mode 0: Cf = D + bias (+res)   mode 1: gelu->fp16   mode 2: ->fp16
#define PL_AH 0
#define PL_BH 8192
#define MSTAGE 16384
#define MM_SMEM (3 * MSTAGE)    // 49152
#define MBK 32

__global__ __launch_bounds__(256) void mm_gemm(
    const __half* __restrict__ Ahp, const __half* __restrict__ Bhp,
    const float* __restrict__ bias, const float* __restrict__ res,
    float* __restrict__ Cf, __half* __restrict__ Ch,
    int N, int K, int mode)
{
    extern __shared__ char smem[];
    uint32_t sb = smem_u32(smem);
    const int tid = threadIdx.x, lane = tid & 31, warp = tid >> 5;
    const int wm = warp & 3, wn = warp >> 2;        // 4 x 2 warp grid
    const int row0 = blockIdx.y * 128, col0 = blockIdx.x * 128;

    const int lr_ = tid >> 1;
    const int cb_ = (tid & 1) * 2;
    const __half* Agh = Ahp + (size_t)(row0 + lr_) * K + cb_ * 8;
    const __half* Bgh = Bhp + (size_t)(col0 + lr_) * K + cb_ * 8;
    const uint32_t sA0 = toff(lr_, cb_), sA1 = toff(lr_, cb_ + 1);

    float d[2][8][4];
    #pragma unroll
    for (int i = 0; i < 2; i++)
        #pragma unroll
        for (int j = 0; j < 8; j++)
            d[i][j][0] = d[i][j][1] = d[i][j][2] = d[i][j][3] = 0.f;

    const int nk = K / MBK;

    #define MM_ISSUE(kt, stg) do {                                   \
        uint32_t bse = sb + (stg) * MSTAGE;                          \
        const __half* p_;                                            \
        p_ = Agh + (kt) * MBK;                                       \
        cp16(bse + PL_AH + sA0, p_); cp16(bse + PL_AH + sA1, p_ + 8);\
        p_ = Bgh + (kt) * MBK;                                       \
        cp16(bse + PL_BH + sA0, p_); cp16(bse + PL_BH + sA1, p_ + 8);\
        CP_COMMIT;                                                   \
    } while (0)

    MM_ISSUE(0, 0);
    if (nk > 1) MM_ISSUE(1, 1);

    const int g = lane >> 3, lq = lane & 7;

    for (int kt = 0; kt < nk; kt++) {
        if (kt + 1 < nk) { CP_WAIT1; } else { CP_WAIT0; }
        __syncthreads();
        if (kt + 2 < nk) {
            int stg2 = (kt + 2) % 3;
            MM_ISSUE(kt + 2, stg2);
        }
        const uint32_t base = sb + (kt % 3) * MSTAGE;

        #pragma unroll
        for (int ks = 0; ks < 2; ks++) {
            uint32_t ah[2][4], bh[8][2];
            const int arow = ((g & 1) << 3) + lq;
            const int acol = 2 * ks + (g >> 1);
            #pragma unroll
            for (int mi = 0; mi < 2; mi++) {
                uint32_t o = toff(wm * 32 + mi * 16 + arow, acol);
                ldsm_x4(ah[mi][0], ah[mi][1], ah[mi][2], ah[mi][3], base + PL_AH + o);
            }
            const int brow = ((g >> 1) << 3) + lq;
            const int bcol = 2 * ks + (g & 1);
            #pragma unroll
            for (int nh = 0; nh < 4; nh++) {
                uint32_t o = toff(wn * 64 + nh * 16 + brow, bcol);
                uint32_t t0, t1, t2, t3;
                ldsm_x4(t0, t1, t2, t3, base + PL_BH + o);
                bh[nh*2][0] = t0; bh[nh*2][1] = t1;
                bh[nh*2+1][0] = t2; bh[nh*2+1][1] = t3;
            }
            #pragma unroll
            for (int mi = 0; mi < 2; mi++)
                #pragma unroll
                for (int ni = 0; ni < 8; ni++)
                    mma16816(d[mi][ni], ah[mi], bh[ni]);
        }
    }

    // ---- epilogue ----
    const int rr = lane >> 2, cc2 = (lane & 3) * 2;
    float bch[8][2];
    #pragma unroll
    for (int ni = 0; ni < 8; ni++) {
        int cg = col0 + wn * 64 + ni * 8 + cc2;
        bch[ni][0] = bias[cg]; bch[ni][1] = bias[cg + 1];
    }
    #pragma unroll
    for (int mi = 0; mi < 2; mi++) {
        #pragma unroll
        for (int ni = 0; ni < 8; ni++) {
            int r0g = row0 + wm * 32 + mi * 16 + rr;
            int cg  = col0 + wn * 64 + ni * 8 + cc2;
            #pragma unroll
            for (int hrow = 0; hrow < 2; hrow++) {
                int r = r0g + hrow * 8;
                float v0 = d[mi][ni][hrow * 2 + 0] + bch[ni][0];
                float v1 = d[mi][ni][hrow * 2 + 1] + bch[ni][1];
                if (mode == 0) {
                    if (res) {
                        float2 rv = *(const float2*)(res + (size_t)r * N + cg);
                        v0 += rv.x; v1 += rv.y;
                    }
                    float2 o; o.x = v0; o.y = v1;
                    *(float2*)(Cf + (size_t)r * N + cg) = o;
                } else {
                    if (mode == 1) { v0 = gelu_tanh(v0); v1 = gelu_tanh(v1); }
                    *(uint32_t*)(Ch + (size_t)r * N + cg) = packhf(v0, v1);
                }
            }
        }
    }
}

// ------------------- tensor-core flash attention (fp16) --------------------
// 4 warps, 64 q x 64 k tiles, D=64.
#define AT_Q  0
#define AT_K  8192
#define AT_V  16384
#define AT_MD 24576
#define AT_SMEM 24832

__global__ __launch_bounds__(128) void attn_tc(
    const __half* __restrict__ Qp, const __half* __restrict__ Kp,
    const __half* __restrict__ Vp, __half* __restrict__ Op,
    const int* __restrict__ maskp,
    int qStride, int kvStride, int Lk, float scale)
{
    extern __shared__ char smem[];
    uint32_t sb = smem_u32(smem);
    const int tid = threadIdx.x, lane = tid & 31, warp = tid >> 5;
    const int b = blockIdx.z, h = blockIdx.y, n0 = blockIdx.x * 64;
    const int w16 = warp * 16;

    #pragma unroll
    for (int it = 0; it < 4; it++) {
        int cid = tid + it * 128;
        int r = cid >> 3, c = cid & 7;
        size_t gq = (size_t)(b * Nn + n0 + r) * qStride + h * Dd + c * 8;
        cp16(sb + AT_Q + aoff(r, c), Qp + gq);
    }
    CP_COMMIT; CP_WAIT0;
    __syncthreads();

    uint32_t qh[4][4];
    {
        int rr = (lane & 7) + 8 * ((lane >> 3) & 1);
        int cc = lane >> 4;
        #pragma unroll
        for (int kc = 0; kc < 4; kc++) {
            uint32_t o = aoff(w16 + rr, kc * 2 + cc);
            ldsm_x4(qh[kc][0], qh[kc][1], qh[kc][2], qh[kc][3], sb + AT_Q + o);
        }
    }

    float o_[8][4];
    #pragma unroll
    for (int i = 0; i < 8; i++) { o_[i][0]=o_[i][1]=o_[i][2]=o_[i][3]=0.f; }
    float m0 = -INFINITY, m1 = -INFINITY, l0 = 0.f, l1 = 0.f;

    const int krow = (lane & 7) + 8 * (lane >> 4);
    const int kcsel = (lane >> 3) & 1;
    const int vrow = lane & 15, vcsel = lane >> 4;
    const float* madd = (const float*)(smem + AT_MD);

    const int nTiles = Lk >> 6;
    for (int kt = 0; kt < nTiles; kt++) {
        __syncthreads();
        #pragma unroll
        for (int it = 0; it < 4; it++) {
            int cid = tid + it * 128;
            int r = cid >> 3, c = cid & 7;
            size_t gk = (size_t)(b * Lk + kt * 64 + r) * kvStride + h * Dd + c * 8;
            uint32_t o = aoff(r, c);
            cp16(sb + AT_K + o, Kp + gk);
            cp16(sb + AT_V + o, Vp + gk);
        }
        if (maskp && tid < 64)
            ((float*)(smem + AT_MD))[tid] =
                maskp[b * Lk + kt * 64 + tid] ? 0.f : -1e30f;
        CP_COMMIT; CP_WAIT0;
        __syncthreads();

        float s[8][4];
        #pragma unroll
        for (int i = 0; i < 8; i++) { s[i][0]=s[i][1]=s[i][2]=s[i][3]=0.f; }
        #pragma unroll
        for (int kc = 0; kc < 4; kc++) {
            #pragma unroll
            for (int np = 0; np < 4; np++) {
                uint32_t o = aoff(np * 16 + krow, kc * 2 + kcsel);
                uint32_t h0, h1, h2, h3;
                ldsm_x4(h0, h1, h2, h3, sb + AT_K + o);
                uint32_t bhA[2] = {h0, h1}, bhB[2] = {h2, h3};
                mma16816(s[np*2],   qh[kc], bhA);
                mma16816(s[np*2+1], qh[kc], bhB);
            }
        }
        #pragma unroll
        for (int nt = 0; nt < 8; nt++) {
            s[nt][0] *= scale; s[nt][1] *= scale;
            s[nt][2] *= scale; s[nt][3] *= scale;
        }
        if (maskp) {
            int cbase = 2 * (lane & 3);
            #pragma unroll
            for (int nt = 0; nt < 8; nt++) {
                float mA = madd[nt * 8 + cbase], mB = madd[nt * 8 + cbase + 1];
                s[nt][0] += mA; s[nt][1] += mB;
                s[nt][2] += mA; s[nt][3] += mB;
            }
        }
        float lm0 = -INFINITY, lm1 = -INFINITY;
        #pragma unroll
        for (int nt = 0; nt < 8; nt++) {
            lm0 = fmaxf(lm0, fmaxf(s[nt][0], s[nt][1]));
            lm1 = fmaxf(lm1, fmaxf(s[nt][2], s[nt][3]));
        }
        lm0 = fmaxf(lm0, __shfl_xor_sync(0xffffffffu, lm0, 1));
        lm0 = fmaxf(lm0, __shfl_xor_sync(0xffffffffu, lm0, 2));
        lm1 = fmaxf(lm1, __shfl_xor_sync(0xffffffffu, lm1, 1));
        lm1 = fmaxf(lm1, __shfl_xor_sync(0xffffffffu, lm1, 2));
        float mn0 = fmaxf(m0, lm0), mn1 = fmaxf(m1, lm1);
        float cr0 = __expf(m0 - mn0), cr1 = __expf(m1 - mn1);
        float sum0 = 0.f, sum1 = 0.f;
        #pragma unroll
        for (int nt = 0; nt < 8; nt++) {
            s[nt][0] = __expf(s[nt][0] - mn0); sum0 += s[nt][0];
            s[nt][1] = __expf(s[nt][1] - mn0); sum0 += s[nt][1];
            s[nt][2] = __expf(s[nt][2] - mn1); sum1 += s[nt][2];
            s[nt][3] = __expf(s[nt][3] - mn1); sum1 += s[nt][3];
        }
        sum0 += __shfl_xor_sync(0xffffffffu, sum0, 1);
        sum0 += __shfl_xor_sync(0xffffffffu, sum0, 2);
        sum1 += __shfl_xor_sync(0xffffffffu, sum1, 1);
        sum1 += __shfl_xor_sync(0xffffffffu, sum1, 2);
        l0 = l0 * cr0 + sum0; l1 = l1 * cr1 + sum1;
        m0 = mn0; m1 = mn1;
        #pragma unroll
        for (int nt = 0; nt < 8; nt++) {
            o_[nt][0] *= cr0; o_[nt][1] *= cr0;
            o_[nt][2] *= cr1; o_[nt][3] *= cr1;
        }
        #pragma unroll
        for (int kc = 0; kc < 4; kc++) {
            uint32_t pah[4];
            float* sA = s[kc * 2];
            float* sB = s[kc * 2 + 1];
            pah[0] = packhf(sA[0], sA[1]); pah[1] = packhf(sA[2], sA[3]);
            pah[2] = packhf(sB[0], sB[1]); pah[3] = packhf(sB[2], sB[3]);
            #pragma unroll
            for (int dp = 0; dp < 4; dp++) {
                uint32_t o = aoff(kc * 16 + vrow, dp * 2 + vcsel);
                uint32_t v0, v1, v2, v3;
                ldsm_x4t(v0, v1, v2, v3, sb + AT_V + o);
                uint32_t bhA[2] = {v0, v1}, bhB[2] = {v2, v3};
                mma16816(o_[dp*2],   pah, bhA);
                mma16816(o_[dp*2+1], pah, bhB);
            }
        }
    }

    float inv0 = 1.0f / l0, inv1 = 1.0f / l1;
    int r0 = w16 + (lane >> 2);
    int cg = h * Dd + 2 * (lane & 3);
    size_t rb = (size_t)(b * Nn + n0);
    #pragma unroll
    for (int nt = 0; nt < 8; nt++) {
        float v0 = o_[nt][0] * inv0, v1 = o_[nt][1] * inv0;
        float w0 = o_[nt][2] * inv1, w1 = o_[nt][3] * inv1;
        *(uint32_t*)(Op + (rb + r0) * Cc + cg + nt * 8) = packhf(v0, v1);
        *(uint32_t*)(Op + (rb + r0 + 8) * Cc + cg + nt * 8) = packhf(w0, w1);
    }
}

// ------------------------------- launch ------------------------------------
static void* sym_addr(const void* sym) {
    void* p = nullptr;
    cudaGetSymbolAddress(&p, sym);
    return p;
}

extern "C" void kernel_launch(void* const* d_in, const int* in_sizes, int n_in,
                              void* d_out, int out_size)
{
    const float* x        = (const float*)d_in[0];
    const float* c_dino   = (const float*)d_in[1];
    const float* c_text   = (const float*)d_in[2];
    const int*   mask     = (const int*)  d_in[3];
    const float* W_ada    = (const float*)d_in[4];
    const float* b_ada    = (const float*)d_in[5];
    const float* W_qkv    = (const float*)d_in[6];
    const float* b_qkv    = (const float*)d_in[7];
    const float* W_psa    = (const float*)d_in[8];
    const float* b_psa    = (const float*)d_in[9];
    const float* W_q      = (const float*)d_in[10];
    const float* b_q      = (const float*)d_in[11];
    const float* W_kv     = (const float*)d_in[12];
    const float* b_kv     = (const float*)d_in[13];
    const float* W_pca    = (const float*)d_in[14];
    const float* b_pca    = (const float*)d_in[15];
    const float* W_fc1    = (const float*)d_in[16];
    const float* b_fc1    = (const float*)d_in[17];
    const float* W_fc2    = (const float*)d_in[18];
    const float* b_fc2    = (const float*)d_in[19];
    float* out = (float*)d_out;

    float* ada = (float*)sym_addr(g_ada);
    float* x1  = (float*)sym_addr(g_x1);
    float* x2  = (float*)sym_addr(g_x2);

    __half* hb   = (__half*)sym_addr(g_h);
    __half* qkv  = (__half*)sym_addr(g_qkv);
    __half* kv   = (__half*)sym_addr(g_kv);
    __half* ct   = (__half*)sym_addr(g_ct);
    __half* at   = (__half*)sym_addr(g_at);
    __half* mlp  = (__half*)sym_addr(g_mlp);

    __half* wqkv = (__half*)sym_addr(g_wqkv);
    __half* wpsa = (__half*)sym_addr(g_wpsa);
    __half* wq   = (__half*)sym_addr(g_wq);
    __half* wkv  = (__half*)sym_addr(g_wkv);
    __half* wpca = (__half*)sym_addr(g_wpca);
    __half* wfc1 = (__half*)sym_addr(g_wfc1);
    __half* wfc2 = (__half*)sym_addr(g_wfc2);

    cudaFuncSetAttribute(attn_tc, cudaFuncAttributeMaxDynamicSharedMemorySize, AT_SMEM);
    cudaFuncSetAttribute(mm_gemm, cudaFuncAttributeMaxDynamicSharedMemorySize, MM_SMEM);

    // ---- weight prep ----
    wprep_kernel<<<dim3(3*Cc/32, Cc/32), 256>>>(W_qkv, wqkv, Cc, 3*Cc);
    wprep_kernel<<<dim3(Cc/32,   Cc/32), 256>>>(W_psa, wpsa, Cc, Cc);
    wprep_kernel<<<dim3(Cc/32,   Cc/32), 256>>>(W_q,   wq,   Cc, Cc);
    wprep_kernel<<<dim3(2*Cc/32, Cc/32), 256>>>(W_kv,  wkv,  Cc, 2*Cc);
    wprep_kernel<<<dim3(Cc/32,   Cc/32), 256>>>(W_pca, wpca, Cc, Cc);
    wprep_kernel<<<dim3(MLPD/32, Cc/32), 256>>>(W_fc1, wfc1, Cc, MLPD);
    wprep_kernel<<<dim3(Cc/32, MLPD/32), 256>>>(W_fc2, wfc2, MLPD, Cc);

    ada_kernel<<<dim3(24, Bc), 256>>>(c_dino, W_ada, b_ada, ada);
    ct_split_kernel<<<(Bc*Mm*Cc)/1024, 256>>>(c_text, ct);

    // ---- self attention ----
    lnmod_kernel<<<ROWS, 256>>>(x, ada, 0, hb);
    mm_gemm<<<dim3(3*Cc/128, ROWS/128), 256, MM_SMEM>>>(
        hb, wqkv, b_qkv, nullptr, nullptr, qkv, 3*Cc, Cc, 2);
    attn_tc<<<dim3(Nn/64, Hh, Bc), 128, AT_SMEM>>>(
        qkv, qkv + Cc, qkv + 2*Cc, at, nullptr, 3*Cc, 3*Cc, Nn, 0.125f);
    mm_gemm<<<dim3(Cc/128, ROWS/128), 256, MM_SMEM>>>(
        at, wpsa, b_psa, x, x1, nullptr, Cc, Cc, 0);

    // ---- cross attention ----
    lnmod_kernel<<<ROWS, 256>>>(x1, ada, 2*Cc, hb);
    mm_gemm<<<dim3(Cc/128, ROWS/128), 256, MM_SMEM>>>(
        hb, wq, b_q, nullptr, nullptr, qkv, Cc, Cc, 2);
    mm_gemm<<<dim3(2*Cc/128, (Bc*Mm)/128), 256, MM_SMEM>>>(
        ct, wkv, b_kv, nullptr, nullptr, kv, 2*Cc, Cc, 2);
    attn_tc<<<dim3(Nn/64, Hh, Bc), 128, AT_SMEM>>>(
        qkv, kv, kv + Cc, at, mask, Cc, 2*Cc, Mm, 0.125f);
    mm_gemm<<<dim3(Cc/128, ROWS/128), 256, MM_SMEM>>>(
        at, wpca, b_pca, x1, x2, nullptr, Cc, Cc, 0);

    // ---- MLP ----
    lnmod_kernel<<<ROWS, 256>>>(x2, ada, 4*Cc, hb);
    mm_gemm<<<dim3(MLPD/128, ROWS/128), 256, MM_SMEM>>>(
        hb, wfc1, b_fc1, nullptr, nullptr, mlp, MLPD, Cc, 1);
    mm_gemm<<<dim3(Cc/128, ROWS/128), 256, MM_SMEM>>>(
        mlp, wfc2, b_fc2, x2, out, nullptr, Cc, MLPD, 0);
}

// round 11
// speedup vs baseline: 2.1866x; 1.1786x over previous
#include <cuda_runtime.h>
#include <cuda_fp16.h>
#include <math.h>
#include <stdint.h>

// ---------------------------------------------------------------------------
// DiT block, pure fp16 tensor-core pipeline (fp32 accumulate everywhere).
// GEMM: tile 128x128x64 chunks (MBK=64), 3-stage cp.async pipeline,
// 128B-row swizzled smem, 2 CTAs/SM.
// B=8, N=1024, M=128, C=1024, H=16, D=64, MLP=4096
// ---------------------------------------------------------------------------

#define Bc  8
#define Nn  1024
#define Mm  128
#define Cc  1024
#define Hh  16
#define Dd  64
#define MLPD 4096
#define ROWS (Bc * Nn)          // 8192

// ------------------------- scratch (device globals) ------------------------
__device__ float g_ada[Bc * 6 * Cc];
__device__ float g_x1[ROWS * Cc];
__device__ float g_x2[ROWS * Cc];

__device__ __align__(16) __half g_h[ROWS * Cc];
__device__ __align__(16) __half g_qkv[ROWS * 3 * Cc];
__device__ __align__(16) __half g_kv[Bc * Mm * 2 * Cc];
__device__ __align__(16) __half g_ct[Bc * Mm * Cc];
__device__ __align__(16) __half g_at[ROWS * Cc];
__device__ __align__(16) __half g_mlp[ROWS * MLPD];

__device__ __align__(16) __half g_wqkv[Cc * 3 * Cc];
__device__ __align__(16) __half g_wpsa[Cc * Cc];
__device__ __align__(16) __half g_wq[Cc * Cc];
__device__ __align__(16) __half g_wkv[Cc * 2 * Cc];
__device__ __align__(16) __half g_wpca[Cc * Cc];
__device__ __align__(16) __half g_wfc1[Cc * MLPD];
__device__ __align__(16) __half g_wfc2[MLPD * Cc];

// ------------------------------ ptx helpers --------------------------------
__device__ __forceinline__ uint32_t smem_u32(const void* p) {
    uint32_t a;
    asm("{ .reg .u64 t; cvta.to.shared.u64 t, %1; cvt.u32.u64 %0, t; }" : "=r"(a) : "l"(p));
    return a;
}
__device__ __forceinline__ void ldsm_x4(uint32_t& r0, uint32_t& r1, uint32_t& r2,
                                        uint32_t& r3, uint32_t a) {
    asm volatile("ldmatrix.sync.aligned.m8n8.x4.shared.b16 {%0,%1,%2,%3}, [%4];"
                 : "=r"(r0), "=r"(r1), "=r"(r2), "=r"(r3) : "r"(a));
}
__device__ __forceinline__ void ldsm_x4t(uint32_t& r0, uint32_t& r1, uint32_t& r2,
                                         uint32_t& r3, uint32_t a) {
    asm volatile("ldmatrix.sync.aligned.m8n8.x4.trans.shared.b16 {%0,%1,%2,%3}, [%4];"
                 : "=r"(r0), "=r"(r1), "=r"(r2), "=r"(r3) : "r"(a));
}
__device__ __forceinline__ void mma16816(float* d, const uint32_t* a, const uint32_t* b) {
    asm volatile(
        "mma.sync.aligned.m16n8k16.row.col.f32.f16.f16.f32 "
        "{%0,%1,%2,%3}, {%4,%5,%6,%7}, {%8,%9}, {%0,%1,%2,%3};"
        : "+f"(d[0]), "+f"(d[1]), "+f"(d[2]), "+f"(d[3])
        : "r"(a[0]), "r"(a[1]), "r"(a[2]), "r"(a[3]), "r"(b[0]), "r"(b[1]));
}
__device__ __forceinline__ void cp16(uint32_t dst, const void* src) {
    asm volatile("cp.async.cg.shared.global [%0], [%1], 16;" :: "r"(dst), "l"(src));
}
#define CP_COMMIT asm volatile("cp.async.commit_group;" ::: "memory")
#define CP_WAIT0  asm volatile("cp.async.wait_group 0;" ::: "memory")
#define CP_WAIT1  asm volatile("cp.async.wait_group 1;" ::: "memory")

// 128B-row swizzle (8 chunks of 16B per row), ldmatrix conflict-free
__device__ __forceinline__ uint32_t aoff(int r, int c) {
    return ((uint32_t)r << 7) + ((uint32_t)((c ^ (r & 7)) & 7) << 4);
}

// ------------------------------ misc helpers -------------------------------
__device__ __forceinline__ float gelu_tanh(float x) {
    float x3 = x * x * x;
    return 0.5f * x * (1.0f + tanhf(0.7978845608028654f * (x + 0.044715f * x3)));
}
__device__ __forceinline__ float block_sum_1024(float v) {
    __shared__ float red[8];
    __shared__ float bcast;
    int lane = threadIdx.x & 31, wid = threadIdx.x >> 5;
    #pragma unroll
    for (int o = 16; o; o >>= 1) v += __shfl_xor_sync(0xffffffffu, v, o);
    __syncthreads();
    if (lane == 0) red[wid] = v;
    __syncthreads();
    if (threadIdx.x == 0) {
        float t = 0.f;
        #pragma unroll
        for (int i = 0; i < 8; i++) t += red[i];
        bcast = t;
    }
    __syncthreads();
    return bcast;
}
__device__ __forceinline__ uint32_t packhf(float x, float y) {
    __half2 p = __floats2half2_rn(x, y);
    return *(uint32_t*)&p;
}

// -------------------- weight prep: W[K][N] -> Wt fp16 [N][K] ----------------
__global__ __launch_bounds__(256) void wprep_kernel(
    const float* __restrict__ W, __half* __restrict__ Th, int K, int N)
{
    __shared__ float t[32][33];
    int n0 = blockIdx.x * 32, k0 = blockIdx.y * 32;
    int tx = threadIdx.x & 31, ty = threadIdx.x >> 5;
    #pragma unroll
    for (int i = 0; i < 32; i += 8)
        t[ty + i][tx] = W[(size_t)(k0 + ty + i) * N + n0 + tx];
    __syncthreads();
    #pragma unroll
    for (int i = 0; i < 32; i += 8)
        Th[(size_t)(n0 + ty + i) * K + k0 + tx] = __float2half_rn(t[tx][ty + i]);
}

// ------------------ c_text -> fp16 ----------------------------------------
__global__ __launch_bounds__(256) void ct_split_kernel(
    const float* __restrict__ X, __half* __restrict__ Ph)
{
    size_t i = ((size_t)blockIdx.x * 256 + threadIdx.x) * 4;
    float4 v = *(const float4*)(X + i);
    uint2 vh;
    vh.x = packhf(v.x, v.y); vh.y = packhf(v.z, v.w);
    *(uint2*)(Ph + i) = vh;
}

// ----------------------- ada = silu(c_dino) @ W_ada + b --------------------
__global__ __launch_bounds__(256) void ada_kernel(
    const float* __restrict__ cdino, const float* __restrict__ W,
    const float* __restrict__ bvec, float* __restrict__ out)
{
    __shared__ float s[Cc];
    int b = blockIdx.y, tid = threadIdx.x;
    for (int i = tid; i < Cc; i += 256) {
        float v = cdino[b * Cc + i];
        s[i] = v / (1.0f + __expf(-v));
    }
    __syncthreads();
    int n = blockIdx.x * 256 + tid;
    float acc = 0.f;
    #pragma unroll 4
    for (int k = 0; k < Cc; k++)
        acc = fmaf(s[k], W[(size_t)k * (6 * Cc) + n], acc);
    out[b * 6 * Cc + n] = acc + bvec[n];
}

// ---------- h = modulate(ln(x), shift, scale) -> fp16 ----------------------
__global__ __launch_bounds__(256) void lnmod_kernel(
    const float* __restrict__ X, const float* __restrict__ ada,
    int shiftOff, __half* __restrict__ Yh)
{
    int row = blockIdx.x;
    int b = row >> 10;
    const float* xr = X + (size_t)row * Cc;
    int c = threadIdx.x * 4;

    float4 v = *(const float4*)(xr + c);
    float mu = block_sum_1024(v.x + v.y + v.z + v.w) * (1.0f / Cc);
    float c0 = v.x - mu, c1 = v.y - mu, c2 = v.z - mu, c3 = v.w - mu;
    float var = block_sum_1024(c0*c0 + c1*c1 + c2*c2 + c3*c3) * (1.0f / Cc);
    float rstd = rsqrtf(var + 1e-6f);

    const float* sh = ada + b * 6 * Cc + shiftOff;
    const float* sc = sh + Cc;
    float4 shv = *(const float4*)(sh + c);
    float4 scv = *(const float4*)(sc + c);
    float4 o;
    o.x = c0 * rstd * (1.0f + scv.x) + shv.x;
    o.y = c1 * rstd * (1.0f + scv.y) + shv.y;
    o.z = c2 * rstd * (1.0f + scv.z) + shv.z;
    o.w = c3 * rstd * (1.0f + scv.w) + shv.w;
    uint2 vh;
    vh.x = packhf(o.x, o.y); vh.y = packhf(o.z, o.w);
    *(uint2*)(Yh + (size_t)row * Cc + c) = vh;
}

// --------------------------- mma.sync GEMM ---------------------------------
// A fp16 [M][K]; B fp16 [N][K]. CTA tile 128x128, K-chunk 64 (MBK=64),
// 8 warps (4x2), warp tile 32x64, 3-stage cp.async pipeline, 2 CTAs/SM.
// smem tile: 128 rows x 64 fp16 (128B rows, aoff swizzle).
// mode 0: Cf = D + bias (+res)   mode 1: gelu->fp16   mode 2: ->fp16
#define PL_A 0
#define PL_B 16384
#define MSTAGE 32768
#define MM_SMEM (3 * MSTAGE)    // 98304
#define MBK 64

__global__ __launch_bounds__(256, 2) void mm_gemm(
    const __half* __restrict__ Ahp, const __half* __restrict__ Bhp,
    const float* __restrict__ bias, const float* __restrict__ res,
    float* __restrict__ Cf, __half* __restrict__ Ch,
    int N, int K, int mode)
{
    extern __shared__ char smem[];
    uint32_t sb = smem_u32(smem);
    const int tid = threadIdx.x, lane = tid & 31, warp = tid >> 5;
    const int wm = warp & 3, wn = warp >> 2;        // 4 x 2 warp grid
    const int row0 = blockIdx.y * 128, col0 = blockIdx.x * 128;

    // loader: 2 threads per row, each owns 4 consecutive 16B chunks
    const int lr_ = tid >> 1;
    const int cb_ = (tid & 1) * 4;                  // chunk base 0 or 4
    const __half* Agh = Ahp + (size_t)(row0 + lr_) * K + cb_ * 8;
    const __half* Bgh = Bhp + (size_t)(col0 + lr_) * K + cb_ * 8;
    uint32_t sA[4];
    #pragma unroll
    for (int j = 0; j < 4; j++) sA[j] = aoff(lr_, cb_ + j);

    float d[2][8][4];
    #pragma unroll
    for (int i = 0; i < 2; i++)
        #pragma unroll
        for (int j = 0; j < 8; j++)
            d[i][j][0] = d[i][j][1] = d[i][j][2] = d[i][j][3] = 0.f;

    const int nk = K / MBK;

    #define MM_ISSUE(kt, stg) do {                                   \
        uint32_t bse = sb + (stg) * MSTAGE;                          \
        const __half* pA = Agh + (kt) * MBK;                         \
        const __half* pB = Bgh + (kt) * MBK;                         \
        cp16(bse + PL_A + sA[0], pA);                                \
        cp16(bse + PL_A + sA[1], pA + 8);                            \
        cp16(bse + PL_A + sA[2], pA + 16);                           \
        cp16(bse + PL_A + sA[3], pA + 24);                           \
        cp16(bse + PL_B + sA[0], pB);                                \
        cp16(bse + PL_B + sA[1], pB + 8);                            \
        cp16(bse + PL_B + sA[2], pB + 16);                           \
        cp16(bse + PL_B + sA[3], pB + 24);                           \
        CP_COMMIT;                                                   \
    } while (0)

    MM_ISSUE(0, 0);
    if (nk > 1) MM_ISSUE(1, 1);

    const int g = lane >> 3, lq = lane & 7;

    for (int kt = 0; kt < nk; kt++) {
        if (kt + 1 < nk) { CP_WAIT1; } else { CP_WAIT0; }
        __syncthreads();
        if (kt + 2 < nk) {
            int stg2 = (kt + 2) % 3;
            MM_ISSUE(kt + 2, stg2);
        }
        const uint32_t base = sb + (kt % 3) * MSTAGE;

        #pragma unroll
        for (int ks = 0; ks < 4; ks++) {
            uint32_t ah[2][4], bh[8][2];
            const int arow = ((g & 1) << 3) + lq;
            const int acol = 2 * ks + (g >> 1);
            #pragma unroll
            for (int mi = 0; mi < 2; mi++) {
                uint32_t o = aoff(wm * 32 + mi * 16 + arow, acol);
                ldsm_x4(ah[mi][0], ah[mi][1], ah[mi][2], ah[mi][3], base + PL_A + o);
            }
            const int brow = ((g >> 1) << 3) + lq;
            const int bcol = 2 * ks + (g & 1);
            #pragma unroll
            for (int nh = 0; nh < 4; nh++) {
                uint32_t o = aoff(wn * 64 + nh * 16 + brow, bcol);
                uint32_t t0, t1, t2, t3;
                ldsm_x4(t0, t1, t2, t3, base + PL_B + o);
                bh[nh*2][0] = t0; bh[nh*2][1] = t1;
                bh[nh*2+1][0] = t2; bh[nh*2+1][1] = t3;
            }
            #pragma unroll
            for (int mi = 0; mi < 2; mi++)
                #pragma unroll
                for (int ni = 0; ni < 8; ni++)
                    mma16816(d[mi][ni], ah[mi], bh[ni]);
        }
    }

    // ---- epilogue ----
    const int rr = lane >> 2, cc2 = (lane & 3) * 2;
    float bch[8][2];
    #pragma unroll
    for (int ni = 0; ni < 8; ni++) {
        int cg = col0 + wn * 64 + ni * 8 + cc2;
        bch[ni][0] = bias[cg]; bch[ni][1] = bias[cg + 1];
    }
    #pragma unroll
    for (int mi = 0; mi < 2; mi++) {
        #pragma unroll
        for (int ni = 0; ni < 8; ni++) {
            int r0g = row0 + wm * 32 + mi * 16 + rr;
            int cg  = col0 + wn * 64 + ni * 8 + cc2;
            #pragma unroll
            for (int hrow = 0; hrow < 2; hrow++) {
                int r = r0g + hrow * 8;
                float v0 = d[mi][ni][hrow * 2 + 0] + bch[ni][0];
                float v1 = d[mi][ni][hrow * 2 + 1] + bch[ni][1];
                if (mode == 0) {
                    if (res) {
                        float2 rv = *(const float2*)(res + (size_t)r * N + cg);
                        v0 += rv.x; v1 += rv.y;
                    }
                    float2 o; o.x = v0; o.y = v1;
                    *(float2*)(Cf + (size_t)r * N + cg) = o;
                } else {
                    if (mode == 1) { v0 = gelu_tanh(v0); v1 = gelu_tanh(v1); }
                    *(uint32_t*)(Ch + (size_t)r * N + cg) = packhf(v0, v1);
                }
            }
        }
    }
}

// ------------------- tensor-core flash attention (fp16) --------------------
// 4 warps, 64 q x 64 k tiles, D=64.
#define AT_Q  0
#define AT_K  8192
#define AT_V  16384
#define AT_MD 24576
#define AT_SMEM 24832

__global__ __launch_bounds__(128) void attn_tc(
    const __half* __restrict__ Qp, const __half* __restrict__ Kp,
    const __half* __restrict__ Vp, __half* __restrict__ Op,
    const int* __restrict__ maskp,
    int qStride, int kvStride, int Lk, float scale)
{
    extern __shared__ char smem[];
    uint32_t sb = smem_u32(smem);
    const int tid = threadIdx.x, lane = tid & 31, warp = tid >> 5;
    const int b = blockIdx.z, h = blockIdx.y, n0 = blockIdx.x * 64;
    const int w16 = warp * 16;

    #pragma unroll
    for (int it = 0; it < 4; it++) {
        int cid = tid + it * 128;
        int r = cid >> 3, c = cid & 7;
        size_t gq = (size_t)(b * Nn + n0 + r) * qStride + h * Dd + c * 8;
        cp16(sb + AT_Q + aoff(r, c), Qp + gq);
    }
    CP_COMMIT; CP_WAIT0;
    __syncthreads();

    uint32_t qh[4][4];
    {
        int rr = (lane & 7) + 8 * ((lane >> 3) & 1);
        int cc = lane >> 4;
        #pragma unroll
        for (int kc = 0; kc < 4; kc++) {
            uint32_t o = aoff(w16 + rr, kc * 2 + cc);
            ldsm_x4(qh[kc][0], qh[kc][1], qh[kc][2], qh[kc][3], sb + AT_Q + o);
        }
    }

    float o_[8][4];
    #pragma unroll
    for (int i = 0; i < 8; i++) { o_[i][0]=o_[i][1]=o_[i][2]=o_[i][3]=0.f; }
    float m0 = -INFINITY, m1 = -INFINITY, l0 = 0.f, l1 = 0.f;

    const int krow = (lane & 7) + 8 * (lane >> 4);
    const int kcsel = (lane >> 3) & 1;
    const int vrow = lane & 15, vcsel = lane >> 4;
    const float* madd = (const float*)(smem + AT_MD);

    const int nTiles = Lk >> 6;
    for (int kt = 0; kt < nTiles; kt++) {
        __syncthreads();
        #pragma unroll
        for (int it = 0; it < 4; it++) {
            int cid = tid + it * 128;
            int r = cid >> 3, c = cid & 7;
            size_t gk = (size_t)(b * Lk + kt * 64 + r) * kvStride + h * Dd + c * 8;
            uint32_t o = aoff(r, c);
            cp16(sb + AT_K + o, Kp + gk);
            cp16(sb + AT_V + o, Vp + gk);
        }
        if (maskp && tid < 64)
            ((float*)(smem + AT_MD))[tid] =
                maskp[b * Lk + kt * 64 + tid] ? 0.f : -1e30f;
        CP_COMMIT; CP_WAIT0;
        __syncthreads();

        float s[8][4];
        #pragma unroll
        for (int i = 0; i < 8; i++) { s[i][0]=s[i][1]=s[i][2]=s[i][3]=0.f; }
        #pragma unroll
        for (int kc = 0; kc < 4; kc++) {
            #pragma unroll
            for (int np = 0; np < 4; np++) {
                uint32_t o = aoff(np * 16 + krow, kc * 2 + kcsel);
                uint32_t h0, h1, h2, h3;
                ldsm_x4(h0, h1, h2, h3, sb + AT_K + o);
                uint32_t bhA[2] = {h0, h1}, bhB[2] = {h2, h3};
                mma16816(s[np*2],   qh[kc], bhA);
                mma16816(s[np*2+1], qh[kc], bhB);
            }
        }
        #pragma unroll
        for (int nt = 0; nt < 8; nt++) {
            s[nt][0] *= scale; s[nt][1] *= scale;
            s[nt][2] *= scale; s[nt][3] *= scale;
        }
        if (maskp) {
            int cbase = 2 * (lane & 3);
            #pragma unroll
            for (int nt = 0; nt < 8; nt++) {
                float mA = madd[nt * 8 + cbase], mB = madd[nt * 8 + cbase + 1];
                s[nt][0] += mA; s[nt][1] += mB;
                s[nt][2] += mA; s[nt][3] += mB;
            }
        }
        float lm0 = -INFINITY, lm1 = -INFINITY;
        #pragma unroll
        for (int nt = 0; nt < 8; nt++) {
            lm0 = fmaxf(lm0, fmaxf(s[nt][0], s[nt][1]));
            lm1 = fmaxf(lm1, fmaxf(s[nt][2], s[nt][3]));
        }
        lm0 = fmaxf(lm0, __shfl_xor_sync(0xffffffffu, lm0, 1));
        lm0 = fmaxf(lm0, __shfl_xor_sync(0xffffffffu, lm0, 2));
        lm1 = fmaxf(lm1, __shfl_xor_sync(0xffffffffu, lm1, 1));
        lm1 = fmaxf(lm1, __shfl_xor_sync(0xffffffffu, lm1, 2));
        float mn0 = fmaxf(m0, lm0), mn1 = fmaxf(m1, lm1);
        float cr0 = __expf(m0 - mn0), cr1 = __expf(m1 - mn1);
        float sum0 = 0.f, sum1 = 0.f;
        #pragma unroll
        for (int nt = 0; nt < 8; nt++) {
            s[nt][0] = __expf(s[nt][0] - mn0); sum0 += s[nt][0];
            s[nt][1] = __expf(s[nt][1] - mn0); sum0 += s[nt][1];
            s[nt][2] = __expf(s[nt][2] - mn1); sum1 += s[nt][2];
            s[nt][3] = __expf(s[nt][3] - mn1); sum1 += s[nt][3];
        }
        sum0 += __shfl_xor_sync(0xffffffffu, sum0, 1);
        sum0 += __shfl_xor_sync(0xffffffffu, sum0, 2);
        sum1 += __shfl_xor_sync(0xffffffffu, sum1, 1);
        sum1 += __shfl_xor_sync(0xffffffffu, sum1, 2);
        l0 = l0 * cr0 + sum0; l1 = l1 * cr1 + sum1;
        m0 = mn0; m1 = mn1;
        #pragma unroll
        for (int nt = 0; nt < 8; nt++) {
            o_[nt][0] *= cr0; o_[nt][1] *= cr0;
            o_[nt][2] *= cr1; o_[nt][3] *= cr1;
        }
        #pragma unroll
        for (int kc = 0; kc < 4; kc++) {
            uint32_t pah[4];
            float* sA0 = s[kc * 2];
            float* sB0 = s[kc * 2 + 1];
            pah[0] = packhf(sA0[0], sA0[1]); pah[1] = packhf(sA0[2], sA0[3]);
            pah[2] = packhf(sB0[0], sB0[1]); pah[3] = packhf(sB0[2], sB0[3]);
            #pragma unroll
            for (int dp = 0; dp < 4; dp++) {
                uint32_t o = aoff(kc * 16 + vrow, dp * 2 + vcsel);
                uint32_t v0, v1, v2, v3;
                ldsm_x4t(v0, v1, v2, v3, sb + AT_V + o);
                uint32_t bhA[2] = {v0, v1}, bhB[2] = {v2, v3};
                mma16816(o_[dp*2],   pah, bhA);
                mma16816(o_[dp*2+1], pah, bhB);
            }
        }
    }

    float inv0 = 1.0f / l0, inv1 = 1.0f / l1;
    int r0 = w16 + (lane >> 2);
    int cg = h * Dd + 2 * (lane & 3);
    size_t rb = (size_t)(b * Nn + n0);
    #pragma unroll
    for (int nt = 0; nt < 8; nt++) {
        float v0 = o_[nt][0] * inv0, v1 = o_[nt][1] * inv0;
        float w0 = o_[nt][2] * inv1, w1 = o_[nt][3] * inv1;
        *(uint32_t*)(Op + (rb + r0) * Cc + cg + nt * 8) = packhf(v0, v1);
        *(uint32_t*)(Op + (rb + r0 + 8) * Cc + cg + nt * 8) = packhf(w0, w1);
    }
}

// ------------------------------- launch ------------------------------------
static void* sym_addr(const void* sym) {
    void* p = nullptr;
    cudaGetSymbolAddress(&p, sym);
    return p;
}

extern "C" void kernel_launch(void* const* d_in, const int* in_sizes, int n_in,
                              void* d_out, int out_size)
{
    const float* x        = (const float*)d_in[0];
    const float* c_dino   = (const float*)d_in[1];
    const float* c_text   = (const float*)d_in[2];
    const int*   mask     = (const int*)  d_in[3];
    const float* W_ada    = (const float*)d_in[4];
    const float* b_ada    = (const float*)d_in[5];
    const float* W_qkv    = (const float*)d_in[6];
    const float* b_qkv    = (const float*)d_in[7];
    const float* W_psa    = (const float*)d_in[8];
    const float* b_psa    = (const float*)d_in[9];
    const float* W_q      = (const float*)d_in[10];
    const float* b_q      = (const float*)d_in[11];
    const float* W_kv     = (const float*)d_in[12];
    const float* b_kv     = (const float*)d_in[13];
    const float* W_pca    = (const float*)d_in[14];
    const float* b_pca    = (const float*)d_in[15];
    const float* W_fc1    = (const float*)d_in[16];
    const float* b_fc1    = (const float*)d_in[17];
    const float* W_fc2    = (const float*)d_in[18];
    const float* b_fc2    = (const float*)d_in[19];
    float* out = (float*)d_out;

    float* ada = (float*)sym_addr(g_ada);
    float* x1  = (float*)sym_addr(g_x1);
    float* x2  = (float*)sym_addr(g_x2);

    __half* hb   = (__half*)sym_addr(g_h);
    __half* qkv  = (__half*)sym_addr(g_qkv);
    __half* kv   = (__half*)sym_addr(g_kv);
    __half* ct   = (__half*)sym_addr(g_ct);
    __half* at   = (__half*)sym_addr(g_at);
    __half* mlp  = (__half*)sym_addr(g_mlp);

    __half* wqkv = (__half*)sym_addr(g_wqkv);
    __half* wpsa = (__half*)sym_addr(g_wpsa);
    __half* wq   = (__half*)sym_addr(g_wq);
    __half* wkv  = (__half*)sym_addr(g_wkv);
    __half* wpca = (__half*)sym_addr(g_wpca);
    __half* wfc1 = (__half*)sym_addr(g_wfc1);
    __half* wfc2 = (__half*)sym_addr(g_wfc2);

    cudaFuncSetAttribute(attn_tc, cudaFuncAttributeMaxDynamicSharedMemorySize, AT_SMEM);
    cudaFuncSetAttribute(mm_gemm, cudaFuncAttributeMaxDynamicSharedMemorySize, MM_SMEM);

    // ---- weight prep ----
    wprep_kernel<<<dim3(3*Cc/32, Cc/32), 256>>>(W_qkv, wqkv, Cc, 3*Cc);
    wprep_kernel<<<dim3(Cc/32,   Cc/32), 256>>>(W_psa, wpsa, Cc, Cc);
    wprep_kernel<<<dim3(Cc/32,   Cc/32), 256>>>(W_q,   wq,   Cc, Cc);
    wprep_kernel<<<dim3(2*Cc/32, Cc/32), 256>>>(W_kv,  wkv,  Cc, 2*Cc);
    wprep_kernel<<<dim3(Cc/32,   Cc/32), 256>>>(W_pca, wpca, Cc, Cc);
    wprep_kernel<<<dim3(MLPD/32, Cc/32), 256>>>(W_fc1, wfc1, Cc, MLPD);
    wprep_kernel<<<dim3(Cc/32, MLPD/32), 256>>>(W_fc2, wfc2, MLPD, Cc);

    ada_kernel<<<dim3(24, Bc), 256>>>(c_dino, W_ada, b_ada, ada);
    ct_split_kernel<<<(Bc*Mm*Cc)/1024, 256>>>(c_text, ct);

    // ---- self attention ----
    lnmod_kernel<<<ROWS, 256>>>(x, ada, 0, hb);
    mm_gemm<<<dim3(3*Cc/128, ROWS/128), 256, MM_SMEM>>>(
        hb, wqkv, b_qkv, nullptr, nullptr, qkv, 3*Cc, Cc, 2);
    attn_tc<<<dim3(Nn/64, Hh, Bc), 128, AT_SMEM>>>(
        qkv, qkv + Cc, qkv + 2*Cc, at, nullptr, 3*Cc, 3*Cc, Nn, 0.125f);
    mm_gemm<<<dim3(Cc/128, ROWS/128), 256, MM_SMEM>>>(
        at, wpsa, b_psa, x, x1, nullptr, Cc, Cc, 0);

    // ---- cross attention ----
    lnmod_kernel<<<ROWS, 256>>>(x1, ada, 2*Cc, hb);
    mm_gemm<<<dim3(Cc/128, ROWS/128), 256, MM_SMEM>>>(
        hb, wq, b_q, nullptr, nullptr, qkv, Cc, Cc, 2);
    mm_gemm<<<dim3(2*Cc/128, (Bc*Mm)/128), 256, MM_SMEM>>>(
        ct, wkv, b_kv, nullptr, nullptr, kv, 2*Cc, Cc, 2);
    attn_tc<<<dim3(Nn/64, Hh, Bc), 128, AT_SMEM>>>(
        qkv, kv, kv + Cc, at, mask, Cc, 2*Cc, Mm, 0.125f);
    mm_gemm<<<dim3(Cc/128, ROWS/128), 256, MM_SMEM>>>(
        at, wpca, b_pca, x1, x2, nullptr, Cc, Cc, 0);

    // ---- MLP ----
    lnmod_kernel<<<ROWS, 256>>>(x2, ada, 4*Cc, hb);
    mm_gemm<<<dim3(MLPD/128, ROWS/128), 256, MM_SMEM>>>(
        hb, wfc1, b_fc1, nullptr, nullptr, mlp, MLPD, Cc, 1);
    mm_gemm<<<dim3(Cc/128, ROWS/128), 256, MM_SMEM>>>(
        mlp, wfc2, b_fc2, x2, out, nullptr, Cc, MLPD, 0);
}

// round 13
// speedup vs baseline: 2.1950x; 1.0038x over previous
#include <cuda_runtime.h>
#include <cuda_fp16.h>
#include <math.h>
#include <stdint.h>

// ---------------------------------------------------------------------------
// DiT block, pure fp16 tensor-core pipeline (fp32 accumulate everywhere).
// GEMM: 128x128 tile, MBK=64, 3-stage cp.async, 2 CTAs/SM (at mma.sync roof).
// Attention: 64q x 64k flash, double-buffered K/V (load/compute overlap).
// B=8, N=1024, M=128, C=1024, H=16, D=64, MLP=4096
// ---------------------------------------------------------------------------

#define Bc  8
#define Nn  1024
#define Mm  128
#define Cc  1024
#define Hh  16
#define Dd  64
#define MLPD 4096
#define ROWS (Bc * Nn)          // 8192

// ------------------------- scratch (device globals) ------------------------
__device__ float g_ada[Bc * 6 * Cc];
__device__ float g_x1[ROWS * Cc];
__device__ float g_x2[ROWS * Cc];

__device__ __align__(16) __half g_h[ROWS * Cc];
__device__ __align__(16) __half g_qkv[ROWS * 3 * Cc];
__device__ __align__(16) __half g_kv[Bc * Mm * 2 * Cc];
__device__ __align__(16) __half g_ct[Bc * Mm * Cc];
__device__ __align__(16) __half g_at[ROWS * Cc];
__device__ __align__(16) __half g_mlp[ROWS * MLPD];

__device__ __align__(16) __half g_wqkv[Cc * 3 * Cc];
__device__ __align__(16) __half g_wpsa[Cc * Cc];
__device__ __align__(16) __half g_wq[Cc * Cc];
__device__ __align__(16) __half g_wkv[Cc * 2 * Cc];
__device__ __align__(16) __half g_wpca[Cc * Cc];
__device__ __align__(16) __half g_wfc1[Cc * MLPD];
__device__ __align__(16) __half g_wfc2[MLPD * Cc];

// ------------------------------ ptx helpers --------------------------------
__device__ __forceinline__ uint32_t smem_u32(const void* p) {
    uint32_t a;
    asm("{ .reg .u64 t; cvta.to.shared.u64 t, %1; cvt.u32.u64 %0, t; }" : "=r"(a) : "l"(p));
    return a;
}
__device__ __forceinline__ void ldsm_x4(uint32_t& r0, uint32_t& r1, uint32_t& r2,
                                        uint32_t& r3, uint32_t a) {
    asm volatile("ldmatrix.sync.aligned.m8n8.x4.shared.b16 {%0,%1,%2,%3}, [%4];"
                 : "=r"(r0), "=r"(r1), "=r"(r2), "=r"(r3) : "r"(a));
}
__device__ __forceinline__ void ldsm_x4t(uint32_t& r0, uint32_t& r1, uint32_t& r2,
                                         uint32_t& r3, uint32_t a) {
    asm volatile("ldmatrix.sync.aligned.m8n8.x4.trans.shared.b16 {%0,%1,%2,%3}, [%4];"
                 : "=r"(r0), "=r"(r1), "=r"(r2), "=r"(r3) : "r"(a));
}
__device__ __forceinline__ void mma16816(float* d, const uint32_t* a, const uint32_t* b) {
    asm volatile(
        "mma.sync.aligned.m16n8k16.row.col.f32.f16.f16.f32 "
        "{%0,%1,%2,%3}, {%4,%5,%6,%7}, {%8,%9}, {%0,%1,%2,%3};"
        : "+f"(d[0]), "+f"(d[1]), "+f"(d[2]), "+f"(d[3])
        : "r"(a[0]), "r"(a[1]), "r"(a[2]), "r"(a[3]), "r"(b[0]), "r"(b[1]));
}
__device__ __forceinline__ void cp16(uint32_t dst, const void* src) {
    asm volatile("cp.async.cg.shared.global [%0], [%1], 16;" :: "r"(dst), "l"(src));
}
#define CP_COMMIT asm volatile("cp.async.commit_group;" ::: "memory")
#define CP_WAIT0  asm volatile("cp.async.wait_group 0;" ::: "memory")
#define CP_WAIT1  asm volatile("cp.async.wait_group 1;" ::: "memory")

// 128B-row swizzle (8 chunks of 16B per row), ldmatrix conflict-free
__device__ __forceinline__ uint32_t aoff(int r, int c) {
    return ((uint32_t)r << 7) + ((uint32_t)((c ^ (r & 7)) & 7) << 4);
}

// ------------------------------ misc helpers -------------------------------
__device__ __forceinline__ float gelu_tanh(float x) {
    float x3 = x * x * x;
    return 0.5f * x * (1.0f + tanhf(0.7978845608028654f * (x + 0.044715f * x3)));
}
__device__ __forceinline__ float block_sum_1024(float v) {
    __shared__ float red[8];
    __shared__ float bcast;
    int lane = threadIdx.x & 31, wid = threadIdx.x >> 5;
    #pragma unroll
    for (int o = 16; o; o >>= 1) v += __shfl_xor_sync(0xffffffffu, v, o);
    __syncthreads();
    if (lane == 0) red[wid] = v;
    __syncthreads();
    if (threadIdx.x == 0) {
        float t = 0.f;
        #pragma unroll
        for (int i = 0; i < 8; i++) t += red[i];
        bcast = t;
    }
    __syncthreads();
    return bcast;
}
__device__ __forceinline__ uint32_t packhf(float x, float y) {
    __half2 p = __floats2half2_rn(x, y);
    return *(uint32_t*)&p;
}

// -------------------- weight prep: W[K][N] -> Wt fp16 [N][K] ----------------
__global__ __launch_bounds__(256) void wprep_kernel(
    const float* __restrict__ W, __half* __restrict__ Th, int K, int N)
{
    __shared__ float t[32][33];
    int n0 = blockIdx.x * 32, k0 = blockIdx.y * 32;
    int tx = threadIdx.x & 31, ty = threadIdx.x >> 5;
    #pragma unroll
    for (int i = 0; i < 32; i += 8)
        t[ty + i][tx] = W[(size_t)(k0 + ty + i) * N + n0 + tx];
    __syncthreads();
    #pragma unroll
    for (int i = 0; i < 32; i += 8)
        Th[(size_t)(n0 + ty + i) * K + k0 + tx] = __float2half_rn(t[tx][ty + i]);
}

// ------------------ c_text -> fp16 ----------------------------------------
__global__ __launch_bounds__(256) void ct_split_kernel(
    const float* __restrict__ X, __half* __restrict__ Ph)
{
    size_t i = ((size_t)blockIdx.x * 256 + threadIdx.x) * 4;
    float4 v = *(const float4*)(X + i);
    uint2 vh;
    vh.x = packhf(v.x, v.y); vh.y = packhf(v.z, v.w);
    *(uint2*)(Ph + i) = vh;
}

// ----------------------- ada = silu(c_dino) @ W_ada + b --------------------
__global__ __launch_bounds__(256) void ada_kernel(
    const float* __restrict__ cdino, const float* __restrict__ W,
    const float* __restrict__ bvec, float* __restrict__ out)
{
    __shared__ float s[Cc];
    int b = blockIdx.y, tid = threadIdx.x;
    for (int i = tid; i < Cc; i += 256) {
        float v = cdino[b * Cc + i];
        s[i] = v / (1.0f + __expf(-v));
    }
    __syncthreads();
    int n = blockIdx.x * 256 + tid;
    float acc = 0.f;
    #pragma unroll 4
    for (int k = 0; k < Cc; k++)
        acc = fmaf(s[k], W[(size_t)k * (6 * Cc) + n], acc);
    out[b * 6 * Cc + n] = acc + bvec[n];
}

// ---------- h = modulate(ln(x), shift, scale) -> fp16 ----------------------
__global__ __launch_bounds__(256) void lnmod_kernel(
    const float* __restrict__ X, const float* __restrict__ ada,
    int shiftOff, __half* __restrict__ Yh)
{
    int row = blockIdx.x;
    int b = row >> 10;
    const float* xr = X + (size_t)row * Cc;
    int c = threadIdx.x * 4;

    float4 v = *(const float4*)(xr + c);
    float mu = block_sum_1024(v.x + v.y + v.z + v.w) * (1.0f / Cc);
    float c0 = v.x - mu, c1 = v.y - mu, c2 = v.z - mu, c3 = v.w - mu;
    float var = block_sum_1024(c0*c0 + c1*c1 + c2*c2 + c3*c3) * (1.0f / Cc);
    float rstd = rsqrtf(var + 1e-6f);

    const float* sh = ada + b * 6 * Cc + shiftOff;
    const float* sc = sh + Cc;
    float4 shv = *(const float4*)(sh + c);
    float4 scv = *(const float4*)(sc + c);
    float4 o;
    o.x = c0 * rstd * (1.0f + scv.x) + shv.x;
    o.y = c1 * rstd * (1.0f + scv.y) + shv.y;
    o.z = c2 * rstd * (1.0f + scv.z) + shv.z;
    o.w = c3 * rstd * (1.0f + scv.w) + shv.w;
    uint2 vh;
    vh.x = packhf(o.x, o.y); vh.y = packhf(o.z, o.w);
    *(uint2*)(Yh + (size_t)row * Cc + c) = vh;
}

// --------------------------- mma.sync GEMM ---------------------------------
// A fp16 [M][K]; B fp16 [N][K]. CTA tile 128x128, MBK=64, 8 warps (4x2),
// warp tile 32x64, 3-stage cp.async, 2 CTAs/SM, 128B-row aoff swizzle.
// mode 0: Cf = D + bias (+res)   mode 1: gelu->fp16   mode 2: ->fp16
#define PL_A 0
#define PL_B 16384
#define MSTAGE 32768
#define MM_SMEM (3 * MSTAGE)    // 98304
#define MBK 64

__global__ __launch_bounds__(256, 2) void mm_gemm(
    const __half* __restrict__ Ahp, const __half* __restrict__ Bhp,
    const float* __restrict__ bias, const float* __restrict__ res,
    float* __restrict__ Cf, __half* __restrict__ Ch,
    int N, int K, int mode)
{
    extern __shared__ char smem[];
    uint32_t sb = smem_u32(smem);
    const int tid = threadIdx.x, lane = tid & 31, warp = tid >> 5;
    const int wm = warp & 3, wn = warp >> 2;
    const int row0 = blockIdx.y * 128, col0 = blockIdx.x * 128;

    const int lr_ = tid >> 1;
    const int cb_ = (tid & 1) * 4;
    const __half* Agh = Ahp + (size_t)(row0 + lr_) * K + cb_ * 8;
    const __half* Bgh = Bhp + (size_t)(col0 + lr_) * K + cb_ * 8;
    uint32_t sA[4];
    #pragma unroll
    for (int j = 0; j < 4; j++) sA[j] = aoff(lr_, cb_ + j);

    float d[2][8][4];
    #pragma unroll
    for (int i = 0; i < 2; i++)
        #pragma unroll
        for (int j = 0; j < 8; j++)
            d[i][j][0] = d[i][j][1] = d[i][j][2] = d[i][j][3] = 0.f;

    const int nk = K / MBK;

    #define MM_ISSUE(kt, stg) do {                                   \
        uint32_t bse = sb + (stg) * MSTAGE;                          \
        const __half* pA = Agh + (kt) * MBK;                         \
        const __half* pB = Bgh + (kt) * MBK;                         \
        cp16(bse + PL_A + sA[0], pA);                                \
        cp16(bse + PL_A + sA[1], pA + 8);                            \
        cp16(bse + PL_A + sA[2], pA + 16);                           \
        cp16(bse + PL_A + sA[3], pA + 24);                           \
        cp16(bse + PL_B + sA[0], pB);                                \
        cp16(bse + PL_B + sA[1], pB + 8);                            \
        cp16(bse + PL_B + sA[2], pB + 16);                           \
        cp16(bse + PL_B + sA[3], pB + 24);                           \
        CP_COMMIT;                                                   \
    } while (0)

    MM_ISSUE(0, 0);
    if (nk > 1) MM_ISSUE(1, 1);

    const int g = lane >> 3, lq = lane & 7;

    for (int kt = 0; kt < nk; kt++) {
        if (kt + 1 < nk) { CP_WAIT1; } else { CP_WAIT0; }
        __syncthreads();
        if (kt + 2 < nk) {
            int stg2 = (kt + 2) % 3;
            MM_ISSUE(kt + 2, stg2);
        }
        const uint32_t base = sb + (kt % 3) * MSTAGE;

        #pragma unroll
        for (int ks = 0; ks < 4; ks++) {
            uint32_t ah[2][4], bh[8][2];
            const int arow = ((g & 1) << 3) + lq;
            const int acol = 2 * ks + (g >> 1);
            #pragma unroll
            for (int mi = 0; mi < 2; mi++) {
                uint32_t o = aoff(wm * 32 + mi * 16 + arow, acol);
                ldsm_x4(ah[mi][0], ah[mi][1], ah[mi][2], ah[mi][3], base + PL_A + o);
            }
            const int brow = ((g >> 1) << 3) + lq;
            const int bcol = 2 * ks + (g & 1);
            #pragma unroll
            for (int nh = 0; nh < 4; nh++) {
                uint32_t o = aoff(wn * 64 + nh * 16 + brow, bcol);
                uint32_t t0, t1, t2, t3;
                ldsm_x4(t0, t1, t2, t3, base + PL_B + o);
                bh[nh*2][0] = t0; bh[nh*2][1] = t1;
                bh[nh*2+1][0] = t2; bh[nh*2+1][1] = t3;
            }
            #pragma unroll
            for (int mi = 0; mi < 2; mi++)
                #pragma unroll
                for (int ni = 0; ni < 8; ni++)
                    mma16816(d[mi][ni], ah[mi], bh[ni]);
        }
    }

    // ---- epilogue ----
    const int rr = lane >> 2, cc2 = (lane & 3) * 2;
    float bch[8][2];
    #pragma unroll
    for (int ni = 0; ni < 8; ni++) {
        int cg = col0 + wn * 64 + ni * 8 + cc2;
        bch[ni][0] = bias[cg]; bch[ni][1] = bias[cg + 1];
    }
    #pragma unroll
    for (int mi = 0; mi < 2; mi++) {
        #pragma unroll
        for (int ni = 0; ni < 8; ni++) {
            int r0g = row0 + wm * 32 + mi * 16 + rr;
            int cg  = col0 + wn * 64 + ni * 8 + cc2;
            #pragma unroll
            for (int hrow = 0; hrow < 2; hrow++) {
                int r = r0g + hrow * 8;
                float v0 = d[mi][ni][hrow * 2 + 0] + bch[ni][0];
                float v1 = d[mi][ni][hrow * 2 + 1] + bch[ni][1];
                if (mode == 0) {
                    if (res) {
                        float2 rv = *(const float2*)(res + (size_t)r * N + cg);
                        v0 += rv.x; v1 += rv.y;
                    }
                    float2 o; o.x = v0; o.y = v1;
                    *(float2*)(Cf + (size_t)r * N + cg) = o;
                } else {
                    if (mode == 1) { v0 = gelu_tanh(v0); v1 = gelu_tanh(v1); }
                    *(uint32_t*)(Ch + (size_t)r * N + cg) = packhf(v0, v1);
                }
            }
        }
    }
}

// ------------- tensor-core flash attention (fp16, double-buffered) ---------
// 4 warps, 64 q x 64 k tiles, D=64. K/V (+mask) double-buffered via cp.async.
#define AT_Q   0
#define AT_KV  8192         // stage s: K @ AT_KV + s*16384, V @ +8192
#define AT_MD  40960        // stage s: mask @ AT_MD + s*256
#define AT_SMEM 41472

__global__ __launch_bounds__(128) void attn_tc(
    const __half* __restrict__ Qp, const __half* __restrict__ Kp,
    const __half* __restrict__ Vp, __half* __restrict__ Op,
    const int* __restrict__ maskp,
    int qStride, int kvStride, int Lk, float scale)
{
    extern __shared__ char smem[];
    uint32_t sb = smem_u32(smem);
    const int tid = threadIdx.x, lane = tid & 31, warp = tid >> 5;
    const int b = blockIdx.z, h = blockIdx.y, n0 = blockIdx.x * 64;
    const int w16 = warp * 16;

    // Q load (group)
    #pragma unroll
    for (int it = 0; it < 4; it++) {
        int cid = tid + it * 128;
        int r = cid >> 3, c = cid & 7;
        size_t gq = (size_t)(b * Nn + n0 + r) * qStride + h * Dd + c * 8;
        cp16(sb + AT_Q + aoff(r, c), Qp + gq);
    }
    CP_COMMIT;

    const int nTiles = Lk >> 6;
    // prologue: issue tile 0
    {
        uint32_t kvb = sb + AT_KV;
        #pragma unroll
        for (int it = 0; it < 4; it++) {
            int cid = tid + it * 128;
            int r = cid >> 3, c = cid & 7;
            size_t gk = (size_t)(b * Lk + r) * kvStride + h * Dd + c * 8;
            uint32_t o = aoff(r, c);
            cp16(kvb + o, Kp + gk);
            cp16(kvb + 8192 + o, Vp + gk);
        }
        if (maskp && tid < 64)
            ((float*)(smem + AT_MD))[tid] = maskp[b * Lk + tid] ? 0.f : -1e30f;
        CP_COMMIT;
    }
    CP_WAIT0;     // Q + tile 0 in
    __syncthreads();

    uint32_t qh[4][4];
    {
        int rr = (lane & 7) + 8 * ((lane >> 3) & 1);
        int cc = lane >> 4;
        #pragma unroll
        for (int kc = 0; kc < 4; kc++) {
            uint32_t o = aoff(w16 + rr, kc * 2 + cc);
            ldsm_x4(qh[kc][0], qh[kc][1], qh[kc][2], qh[kc][3], sb + AT_Q + o);
        }
    }

    float o_[8][4];
    #pragma unroll
    for (int i = 0; i < 8; i++) { o_[i][0]=o_[i][1]=o_[i][2]=o_[i][3]=0.f; }
    float m0 = -INFINITY, m1 = -INFINITY, l0 = 0.f, l1 = 0.f;

    const int krow = (lane & 7) + 8 * (lane >> 4);
    const int kcsel = (lane >> 3) & 1;
    const int vrow = lane & 15, vcsel = lane >> 4;

    for (int kt = 0; kt < nTiles; kt++) {
        const int stg = kt & 1;
        const uint32_t kb = sb + AT_KV + stg * 16384;
        const uint32_t vb = kb + 8192;
        const float* madd = (const float*)(smem + AT_MD + stg * 256);

        // prefetch tile kt+1 into the other stage (tile kt-1's reads
        // finished before the sync that admitted tile kt)
        if (kt + 1 < nTiles) {
            uint32_t kvb = sb + AT_KV + ((kt + 1) & 1) * 16384;
            #pragma unroll
            for (int it = 0; it < 4; it++) {
                int cid = tid + it * 128;
                int r = cid >> 3, c = cid & 7;
                size_t gk = (size_t)(b * Lk + (kt + 1) * 64 + r) * kvStride + h * Dd + c * 8;
                uint32_t o = aoff(r, c);
                cp16(kvb + o, Kp + gk);
                cp16(kvb + 8192 + o, Vp + gk);
            }
            if (maskp && tid < 64)
                ((float*)(smem + AT_MD + ((kt + 1) & 1) * 256))[tid] =
                    maskp[b * Lk + (kt + 1) * 64 + tid] ? 0.f : -1e30f;
            CP_COMMIT;
        }

        // ---- S = Q K^T on tile kt ----
        float s[8][4];
        #pragma unroll
        for (int i = 0; i < 8; i++) { s[i][0]=s[i][1]=s[i][2]=s[i][3]=0.f; }
        #pragma unroll
        for (int kc = 0; kc < 4; kc++) {
            #pragma unroll
            for (int np = 0; np < 4; np++) {
                uint32_t o = aoff(np * 16 + krow, kc * 2 + kcsel);
                uint32_t h0, h1, h2, h3;
                ldsm_x4(h0, h1, h2, h3, kb + o);
                uint32_t bhA[2] = {h0, h1}, bhB[2] = {h2, h3};
                mma16816(s[np*2],   qh[kc], bhA);
                mma16816(s[np*2+1], qh[kc], bhB);
            }
        }
        #pragma unroll
        for (int nt = 0; nt < 8; nt++) {
            s[nt][0] *= scale; s[nt][1] *= scale;
            s[nt][2] *= scale; s[nt][3] *= scale;
        }
        if (maskp) {
            int cbase = 2 * (lane & 3);
            #pragma unroll
            for (int nt = 0; nt < 8; nt++) {
                float mA = madd[nt * 8 + cbase], mB = madd[nt * 8 + cbase + 1];
                s[nt][0] += mA; s[nt][1] += mB;
                s[nt][2] += mA; s[nt][3] += mB;
            }
        }
        float lm0 = -INFINITY, lm1 = -INFINITY;
        #pragma unroll
        for (int nt = 0; nt < 8; nt++) {
            lm0 = fmaxf(lm0, fmaxf(s[nt][0], s[nt][1]));
            lm1 = fmaxf(lm1, fmaxf(s[nt][2], s[nt][3]));
        }
        lm0 = fmaxf(lm0, __shfl_xor_sync(0xffffffffu, lm0, 1));
        lm0 = fmaxf(lm0, __shfl_xor_sync(0xffffffffu, lm0, 2));
        lm1 = fmaxf(lm1, __shfl_xor_sync(0xffffffffu, lm1, 1));
        lm1 = fmaxf(lm1, __shfl_xor_sync(0xffffffffu, lm1, 2));
        float mn0 = fmaxf(m0, lm0), mn1 = fmaxf(m1, lm1);
        float cr0 = __expf(m0 - mn0), cr1 = __expf(m1 - mn1);
        float sum0 = 0.f, sum1 = 0.f;
        #pragma unroll
        for (int nt = 0; nt < 8; nt++) {
            s[nt][0] = __expf(s[nt][0] - mn0); sum0 += s[nt][0];
            s[nt][1] = __expf(s[nt][1] - mn0); sum0 += s[nt][1];
            s[nt][2] = __expf(s[nt][2] - mn1); sum1 += s[nt][2];
            s[nt][3] = __expf(s[nt][3] - mn1); sum1 += s[nt][3];
        }
        sum0 += __shfl_xor_sync(0xffffffffu, sum0, 1);
        sum0 += __shfl_xor_sync(0xffffffffu, sum0, 2);
        sum1 += __shfl_xor_sync(0xffffffffu, sum1, 1);
        sum1 += __shfl_xor_sync(0xffffffffu, sum1, 2);
        l0 = l0 * cr0 + sum0; l1 = l1 * cr1 + sum1;
        m0 = mn0; m1 = mn1;
        #pragma unroll
        for (int nt = 0; nt < 8; nt++) {
            o_[nt][0] *= cr0; o_[nt][1] *= cr0;
            o_[nt][2] *= cr1; o_[nt][3] *= cr1;
        }
        #pragma unroll
        for (int kc = 0; kc < 4; kc++) {
            uint32_t pah[4];
            float* sA0 = s[kc * 2];
            float* sB0 = s[kc * 2 + 1];
            pah[0] = packhf(sA0[0], sA0[1]); pah[1] = packhf(sA0[2], sA0[3]);
            pah[2] = packhf(sB0[0], sB0[1]); pah[3] = packhf(sB0[2], sB0[3]);
            #pragma unroll
            for (int dp = 0; dp < 4; dp++) {
                uint32_t o = aoff(kc * 16 + vrow, dp * 2 + vcsel);
                uint32_t v0, v1, v2, v3;
                ldsm_x4t(v0, v1, v2, v3, vb + o);
                uint32_t bhA[2] = {v0, v1}, bhB[2] = {v2, v3};
                mma16816(o_[dp*2],   pah, bhA);
                mma16816(o_[dp*2+1], pah, bhB);
            }
        }

        // admit tile kt+1 (also retires this tile's smem reads before the
        // next prefetch overwrites this stage)
        if (kt + 1 < nTiles) {
            CP_WAIT0;
            __syncthreads();
        }
    }

    float inv0 = 1.0f / l0, inv1 = 1.0f / l1;
    int r0 = w16 + (lane >> 2);
    int cg = h * Dd + 2 * (lane & 3);
    size_t rb = (size_t)(b * Nn + n0);
    #pragma unroll
    for (int nt = 0; nt < 8; nt++) {
        float v0 = o_[nt][0] * inv0, v1 = o_[nt][1] * inv0;
        float w0 = o_[nt][2] * inv1, w1 = o_[nt][3] * inv1;
        *(uint32_t*)(Op + (rb + r0) * Cc + cg + nt * 8) = packhf(v0, v1);
        *(uint32_t*)(Op + (rb + r0 + 8) * Cc + cg + nt * 8) = packhf(w0, w1);
    }
}

// ------------------------------- launch ------------------------------------
static void* sym_addr(const void* sym) {
    void* p = nullptr;
    cudaGetSymbolAddress(&p, sym);
    return p;
}

extern "C" void kernel_launch(void* const* d_in, const int* in_sizes, int n_in,
                              void* d_out, int out_size)
{
    const float* x        = (const float*)d_in[0];
    const float* c_dino   = (const float*)d_in[1];
    const float* c_text   = (const float*)d_in[2];
    const int*   mask     = (const int*)  d_in[3];
    const float* W_ada    = (const float*)d_in[4];
    const float* b_ada    = (const float*)d_in[5];
    const float* W_qkv    = (const float*)d_in[6];
    const float* b_qkv    = (const float*)d_in[7];
    const float* W_psa    = (const float*)d_in[8];
    const float* b_psa    = (const float*)d_in[9];
    const float* W_q      = (const float*)d_in[10];
    const float* b_q      = (const float*)d_in[11];
    const float* W_kv     = (const float*)d_in[12];
    const float* b_kv     = (const float*)d_in[13];
    const float* W_pca    = (const float*)d_in[14];
    const float* b_pca    = (const float*)d_in[15];
    const float* W_fc1    = (const float*)d_in[16];
    const float* b_fc1    = (const float*)d_in[17];
    const float* W_fc2    = (const float*)d_in[18];
    const float* b_fc2    = (const float*)d_in[19];
    float* out = (float*)d_out;

    float* ada = (float*)sym_addr(g_ada);
    float* x1  = (float*)sym_addr(g_x1);
    float* x2  = (float*)sym_addr(g_x2);

    __half* hb   = (__half*)sym_addr(g_h);
    __half* qkv  = (__half*)sym_addr(g_qkv);
    __half* kv   = (__half*)sym_addr(g_kv);
    __half* ct   = (__half*)sym_addr(g_ct);
    __half* at   = (__half*)sym_addr(g_at);
    __half* mlp  = (__half*)sym_addr(g_mlp);

    __half* wqkv = (__half*)sym_addr(g_wqkv);
    __half* wpsa = (__half*)sym_addr(g_wpsa);
    __half* wq   = (__half*)sym_addr(g_wq);
    __half* wkv  = (__half*)sym_addr(g_wkv);
    __half* wpca = (__half*)sym_addr(g_wpca);
    __half* wfc1 = (__half*)sym_addr(g_wfc1);
    __half* wfc2 = (__half*)sym_addr(g_wfc2);

    cudaFuncSetAttribute(attn_tc, cudaFuncAttributeMaxDynamicSharedMemorySize, AT_SMEM);
    cudaFuncSetAttribute(mm_gemm, cudaFuncAttributeMaxDynamicSharedMemorySize, MM_SMEM);

    // ---- weight prep ----
    wprep_kernel<<<dim3(3*Cc/32, Cc/32), 256>>>(W_qkv, wqkv, Cc, 3*Cc);
    wprep_kernel<<<dim3(Cc/32,   Cc/32), 256>>>(W_psa, wpsa, Cc, Cc);
    wprep_kernel<<<dim3(Cc/32,   Cc/32), 256>>>(W_q,   wq,   Cc, Cc);
    wprep_kernel<<<dim3(2*Cc/32, Cc/32), 256>>>(W_kv,  wkv,  Cc, 2*Cc);
    wprep_kernel<<<dim3(Cc/32,   Cc/32), 256>>>(W_pca, wpca, Cc, Cc);
    wprep_kernel<<<dim3(MLPD/32, Cc/32), 256>>>(W_fc1, wfc1, Cc, MLPD);
    wprep_kernel<<<dim3(Cc/32, MLPD/32), 256>>>(W_fc2, wfc2, MLPD, Cc);

    ada_kernel<<<dim3(24, Bc), 256>>>(c_dino, W_ada, b_ada, ada);
    ct_split_kernel<<<(Bc*Mm*Cc)/1024, 256>>>(c_text, ct);

    // ---- self attention ----
    lnmod_kernel<<<ROWS, 256>>>(x, ada, 0, hb);
    mm_gemm<<<dim3(3*Cc/128, ROWS/128), 256, MM_SMEM>>>(
        hb, wqkv, b_qkv, nullptr, nullptr, qkv, 3*Cc, Cc, 2);
    attn_tc<<<dim3(Nn/64, Hh, Bc), 128, AT_SMEM>>>(
        qkv, qkv + Cc, qkv + 2*Cc, at, nullptr, 3*Cc, 3*Cc, Nn, 0.125f);
    mm_gemm<<<dim3(Cc/128, ROWS/128), 256, MM_SMEM>>>(
        at, wpsa, b_psa, x, x1, nullptr, Cc, Cc, 0);

    // ---- cross attention ----
    lnmod_kernel<<<ROWS, 256>>>(x1, ada, 2*Cc, hb);
    mm_gemm<<<dim3(Cc/128, ROWS/128), 256, MM_SMEM>>>(
        hb, wq, b_q, nullptr, nullptr, qkv, Cc, Cc, 2);
    mm_gemm<<<dim3(2*Cc/128, (Bc*Mm)/128), 256, MM_SMEM>>>(
        ct, wkv, b_kv, nullptr, nullptr, kv, 2*Cc, Cc, 2);
    attn_tc<<<dim3(Nn/64, Hh, Bc), 128, AT_SMEM>>>(
        qkv, kv, kv + Cc, at, mask, Cc, 2*Cc, Mm, 0.125f);
    mm_gemm<<<dim3(Cc/128, ROWS/128), 256, MM_SMEM>>>(
        at, wpca, b_pca, x1, x2, nullptr, Cc, Cc, 0);

    // ---- MLP ----
    lnmod_kernel<<<ROWS, 256>>>(x2, ada, 4*Cc, hb);
    mm_gemm<<<dim3(MLPD/128, ROWS/128), 256, MM_SMEM>>>(
        hb, wfc1, b_fc1, nullptr, nullptr, mlp, MLPD, Cc, 1);
    mm_gemm<<<dim3(Cc/128, ROWS/128), 256, MM_SMEM>>>(
        mlp, wfc2, b_fc2, x2, out, nullptr, Cc, MLPD, 0);
}